// round 10
// baseline (speedup 1.0000x reference)
#include <cuda_runtime.h>
#include <cuda_bf16.h>
#include <cuda_fp16.h>
#include <cstdint>

#define CC    256
#define CQ    64
#define NPIX  4096
#define NPAIR 4

// ---------------- helpers ----------------
__device__ __forceinline__ uint32_t smem_u32(const void* p) {
    uint32_t a;
    asm("{ .reg .u64 t; cvta.to.shared.u64 t, %1; cvt.u32.u64 %0, t; }" : "=r"(a) : "l"(p));
    return a;
}

__device__ __forceinline__ void cp16(uint32_t s, const void* g) {
    asm volatile("cp.async.cg.shared.global [%0], [%1], 16;" :: "r"(s), "l"(g) : "memory");
}
#define CP_COMMIT()  asm volatile("cp.async.commit_group;" ::: "memory")
#define CP_WAIT(N)   asm volatile("cp.async.wait_group %0;" :: "n"(N) : "memory")

// m16n8k16 bf16 mma (S phase + proj)
__device__ __forceinline__ void mma16(float c[4], const uint32_t a[4], uint32_t b0, uint32_t b1) {
    asm volatile(
        "mma.sync.aligned.m16n8k16.row.col.f32.bf16.bf16.f32 "
        "{%0,%1,%2,%3}, {%4,%5,%6,%7}, {%8,%9}, {%0,%1,%2,%3};"
        : "+f"(c[0]), "+f"(c[1]), "+f"(c[2]), "+f"(c[3])
        : "r"(a[0]), "r"(a[1]), "r"(a[2]), "r"(a[3]), "r"(b0), "r"(b1));
}

// m16n8k16 fp16 mma (PV phase)
__device__ __forceinline__ void mma16f(float c[4], const uint32_t a[4], uint32_t b0, uint32_t b1) {
    asm volatile(
        "mma.sync.aligned.m16n8k16.row.col.f32.f16.f16.f32 "
        "{%0,%1,%2,%3}, {%4,%5,%6,%7}, {%8,%9}, {%0,%1,%2,%3};"
        : "+f"(c[0]), "+f"(c[1]), "+f"(c[2]), "+f"(c[3])
        : "r"(a[0]), "r"(a[1]), "r"(a[2]), "r"(a[3]), "r"(b0), "r"(b1));
}

__device__ __forceinline__ uint32_t pack_bf16(float a, float b) {
    __nv_bfloat16 h0 = __float2bfloat16(a), h1 = __float2bfloat16(b);
    uint16_t u0 = *(uint16_t*)&h0, u1 = *(uint16_t*)&h1;
    return ((uint32_t)u1 << 16) | u0;
}

__device__ __forceinline__ uint32_t pack_f16(float a, float b) {
    __half2 h = __floats2half2_rn(a, b);
    return *(uint32_t*)&h;
}

// ---------------- scratch ----------------
__device__ float g_Bias[2][384];
__device__ __nv_bfloat16 g_Wh[2][384][CC];
__device__ __nv_bfloat16 g_Wl[2][384][CC];
__device__ __nv_bfloat16 g_Xh[NPAIR][NPIX][CC];
__device__ __nv_bfloat16 g_Xl[NPAIR][NPIX][CC];
__device__ __nv_bfloat16 g_Qh[NPAIR][NPIX][CQ];
__device__ __nv_bfloat16 g_Ql[NPAIR][NPIX][CQ];
__device__ __nv_bfloat16 g_Kh[NPAIR][NPIX][CQ];
__device__ __nv_bfloat16 g_Kl[NPAIR][NPIX][CQ];
__device__ __half g_V[NPAIR][CC][NPIX];          // channel-major fp16 V

// ---------------------------------------------------------------------------
__global__ void prep_weights(
    const float* __restrict__ q1w, const float* __restrict__ q1b,
    const float* __restrict__ k1w, const float* __restrict__ k1b,
    const float* __restrict__ v1w, const float* __restrict__ v1b,
    const float* __restrict__ q2w, const float* __restrict__ q2b,
    const float* __restrict__ k2w, const float* __restrict__ k2b,
    const float* __restrict__ v2w, const float* __restrict__ v2b)
{
    int o = blockIdx.x, s = blockIdx.y;
    const float* w; const float* bsrc; int row;
    if (o < 64)       { w = s ? q2w : q1w; bsrc = s ? q2b : q1b; row = o; }
    else if (o < 128) { w = s ? k2w : k1w; bsrc = s ? k2b : k1b; row = o - 64; }
    else              { w = s ? v2w : v1w; bsrc = s ? v2b : v1b; row = o - 128; }
    float v = w[row * CC + threadIdx.x];
    __nv_bfloat16 h = __float2bfloat16(v);
    g_Wh[s][o][threadIdx.x] = h;
    g_Wl[s][o][threadIdx.x] = __float2bfloat16(v - __bfloat162float(h));
    if (threadIdx.x == 0) g_Bias[s][o] = bsrc[row];
}

// ---------------------------------------------------------------------------
__global__ __launch_bounds__(256) void convert_x(
    const float* __restrict__ in1, const float* __restrict__ in2)
{
    __shared__ float t[64][65];
    int p = blockIdx.z, s = p >> 1, b = p & 1;
    const float* x = (s ? in2 : in1) + (size_t)b * CC * NPIX;
    int n0 = blockIdx.x * 64, c0 = blockIdx.y * 64;
    int tid = threadIdx.x;

    #pragma unroll
    for (int i = 0; i < 4; i++) {
        int m = tid + i * 256;
        int c = m >> 4, nn = (m & 15) << 2;
        float4 v = *(const float4*)&x[(size_t)(c0 + c) * NPIX + n0 + nn];
        t[c][nn] = v.x; t[c][nn + 1] = v.y; t[c][nn + 2] = v.z; t[c][nn + 3] = v.w;
    }
    __syncthreads();

    int n = tid >> 2, cb = (tid & 3) << 4;
    uint32_t hw[8], lw[8];
    #pragma unroll
    for (int j = 0; j < 8; j++) {
        float v0 = t[cb + 2 * j][n], v1 = t[cb + 2 * j + 1][n];
        __nv_bfloat16 h0 = __float2bfloat16(v0);
        __nv_bfloat16 h1 = __float2bfloat16(v1);
        float l0 = v0 - __bfloat162float(h0);
        float l1 = v1 - __bfloat162float(h1);
        uint16_t a0 = *(uint16_t*)&h0, a1 = *(uint16_t*)&h1;
        hw[j] = ((uint32_t)a1 << 16) | a0;
        lw[j] = pack_bf16(l0, l1);
    }
    uint4* dh = (uint4*)&g_Xh[p][n0 + n][c0 + cb];
    uint4* dl = (uint4*)&g_Xl[p][n0 + n][c0 + cb];
    dh[0] = make_uint4(hw[0], hw[1], hw[2], hw[3]);
    dh[1] = make_uint4(hw[4], hw[5], hw[6], hw[7]);
    dl[0] = make_uint4(lw[0], lw[1], lw[2], lw[3]);
    dl[1] = make_uint4(lw[4], lw[5], lw[6], lw[7]);
}

// ---------------------------------------------------------------------------
// Tensorized projection (unchanged)
// ---------------------------------------------------------------------------
#define PJS 144u
#define PA_H 0u
#define PA_L 18432u
#define PB_H 36864u
#define PB_L 55296u
#define PSTAGE 73728u
#define POFF_BIAS 147456u
#define PSMEM 147968u

__global__ __launch_bounds__(256, 1) void proj_mma()
{
    extern __shared__ __align__(16) char psm[];
    uint32_t sb = smem_u32(psm);
    float* bias = (float*)(psm + POFF_BIAS);
    int tid = threadIdx.x;
    int p = blockIdx.z, s = p >> 1;
    int n0 = blockIdx.x * 128, o0 = blockIdx.y * 128;
    int warp = tid >> 5, lane = tid & 31;
    int wm = warp >> 1, wn = warp & 1;
    int r4 = lane >> 2, c4 = lane & 3;

    if (tid < 128) bias[tid] = g_Bias[s][o0 + tid];

    auto issue = [&](int kc) {
        uint32_t st = sb + (uint32_t)(kc & 1) * PSTAGE;
        int k0 = kc * 64;
        #pragma unroll
        for (int i = 0; i < 4; i++) {
            int m = tid + i * 256;
            int r = m >> 3, j = m & 7;
            uint32_t off = (uint32_t)r * PJS + (uint32_t)j * 16u;
            cp16(st + PA_H + off, &g_Xh[p][n0 + r][k0 + j * 8]);
            cp16(st + PA_L + off, &g_Xl[p][n0 + r][k0 + j * 8]);
            cp16(st + PB_H + off, &g_Wh[s][o0 + r][k0 + j * 8]);
            cp16(st + PB_L + off, &g_Wl[s][o0 + r][k0 + j * 8]);
        }
        CP_COMMIT();
    };
    issue(0);
    issue(1);

    float cS[2][8][4] = {};

    for (int kc = 0; kc < 4; kc++) {
        CP_WAIT(1);
        __syncthreads();
        const char* st = psm + (kc & 1) * PSTAGE;

        #pragma unroll
        for (int kt = 0; kt < 4; kt++) {
            int kb = kt * 32 + c4 * 4;
            uint32_t ah[2][4], al[2][4];
            #pragma unroll
            for (int mt = 0; mt < 2; mt++) {
                int r = wm * 32 + mt * 16 + r4;
                const char* a_h = st + PA_H + r * PJS + kb;
                const char* a_l = st + PA_L + r * PJS + kb;
                ah[mt][0] = *(const uint32_t*)a_h;
                ah[mt][1] = *(const uint32_t*)(a_h + 8 * PJS);
                ah[mt][2] = *(const uint32_t*)(a_h + 16);
                ah[mt][3] = *(const uint32_t*)(a_h + 8 * PJS + 16);
                al[mt][0] = *(const uint32_t*)a_l;
                al[mt][1] = *(const uint32_t*)(a_l + 8 * PJS);
                al[mt][2] = *(const uint32_t*)(a_l + 16);
                al[mt][3] = *(const uint32_t*)(a_l + 8 * PJS + 16);
            }
            #pragma unroll
            for (int nt = 0; nt < 8; nt++) {
                int o = wn * 64 + nt * 8 + r4;
                const char* b_h = st + PB_H + o * PJS + kb;
                const char* b_l = st + PB_L + o * PJS + kb;
                uint32_t bh0 = *(const uint32_t*)b_h;
                uint32_t bh1 = *(const uint32_t*)(b_h + 16);
                uint32_t bl0 = *(const uint32_t*)b_l;
                uint32_t bl1 = *(const uint32_t*)(b_l + 16);
                #pragma unroll
                for (int mt = 0; mt < 2; mt++) {
                    mma16(cS[mt][nt], ah[mt], bh0, bh1);
                    mma16(cS[mt][nt], al[mt], bh0, bh1);
                    mma16(cS[mt][nt], ah[mt], bl0, bl1);
                }
            }
        }
        __syncthreads();
        if (kc < 2) issue(kc + 2);
    }

    #pragma unroll
    for (int mt = 0; mt < 2; mt++) {
        int n_lo = n0 + wm * 32 + mt * 16 + r4;
        int n_hi = n_lo + 8;
        #pragma unroll
        for (int nt = 0; nt < 8; nt++) {
            int ol = wn * 64 + nt * 8 + 2 * c4;
            int og = o0 + ol;
            float b0 = bias[ol], b1 = bias[ol + 1];
            float y00 = cS[mt][nt][0] + b0, y01 = cS[mt][nt][1] + b1;
            float y10 = cS[mt][nt][2] + b0, y11 = cS[mt][nt][3] + b1;
            if (og < 64) {
                __nv_bfloat16 h00 = __float2bfloat16(y00), h01 = __float2bfloat16(y01);
                __nv_bfloat16 h10 = __float2bfloat16(y10), h11 = __float2bfloat16(y11);
                uint16_t u00 = *(uint16_t*)&h00, u01 = *(uint16_t*)&h01;
                uint16_t u10 = *(uint16_t*)&h10, u11 = *(uint16_t*)&h11;
                *(uint32_t*)&g_Qh[p][n_lo][og] = ((uint32_t)u01 << 16) | u00;
                *(uint32_t*)&g_Qh[p][n_hi][og] = ((uint32_t)u11 << 16) | u10;
                *(uint32_t*)&g_Ql[p][n_lo][og] =
                    pack_bf16(y00 - __bfloat162float(h00), y01 - __bfloat162float(h01));
                *(uint32_t*)&g_Ql[p][n_hi][og] =
                    pack_bf16(y10 - __bfloat162float(h10), y11 - __bfloat162float(h11));
            } else if (og < 128) {
                int oo = og - 64;
                __nv_bfloat16 h00 = __float2bfloat16(y00), h01 = __float2bfloat16(y01);
                __nv_bfloat16 h10 = __float2bfloat16(y10), h11 = __float2bfloat16(y11);
                uint16_t u00 = *(uint16_t*)&h00, u01 = *(uint16_t*)&h01;
                uint16_t u10 = *(uint16_t*)&h10, u11 = *(uint16_t*)&h11;
                *(uint32_t*)&g_Kh[p][n_lo][oo] = ((uint32_t)u01 << 16) | u00;
                *(uint32_t*)&g_Kh[p][n_hi][oo] = ((uint32_t)u11 << 16) | u10;
                *(uint32_t*)&g_Kl[p][n_lo][oo] =
                    pack_bf16(y00 - __bfloat162float(h00), y01 - __bfloat162float(h01));
                *(uint32_t*)&g_Kl[p][n_hi][oo] =
                    pack_bf16(y10 - __bfloat162float(h10), y11 - __bfloat162float(h11));
            } else {
                int c = og - 128;
                g_V[p][c][n_lo]     = __float2half(y00);
                g_V[p][c + 1][n_lo] = __float2half(y01);
                g_V[p][c][n_hi]     = __float2half(y10);
                g_V[p][c + 1][n_hi] = __float2half(y11);
            }
        }
    }
}

// ---------------------------------------------------------------------------
// Flash attention: 64-row tiles, 8 warps (4M x 2N), 2 CTAs/SM for overlap.
// S bf16 3-term; PV fp16; online row max; O in regs across 64 tiles.
// ---------------------------------------------------------------------------
#define QKSB 144
#define OFF_QH 0u
#define OFF_QL (OFF_QH + 64u * QKSB)               //  9216
#define OFF_KH (OFF_QL + 64u * QKSB)               // 18432
#define OFF_KL (OFF_KH + 64u * QKSB)               // 27648
#define OFF_V  (OFF_KL + 64u * QKSB)               // 36864, 256 ch x 144B fp16
#define OFF_P  (OFF_V + 256u * QKSB)               // 73728, 64 rows x 144B fp16
#define OFF_L  (OFF_P + 64u * QKSB)                // 82944, lrow: 64 f32
#define OFF_PM (OFF_L + 512u)                      // 83456, pmax: 2 x 64 f32
#define SMEM_TOTAL (OFF_PM + 1024u)                // 84480 (x2 CTA = 168960)

__global__ __launch_bounds__(256, 2)
void flash_attn(const float* __restrict__ in1, const float* __restrict__ in2,
                const float* __restrict__ gamma, float* __restrict__ out)
{
    extern __shared__ __align__(16) char smem[];
    float* lrow = (float*)(smem + OFF_L);
    float* pmax = (float*)(smem + OFF_PM);
    uint32_t sb = smem_u32(smem);

    int tid  = threadIdx.x;
    int p    = blockIdx.y;
    int i0   = blockIdx.x * 64;
    int warp = tid >> 5, lane = tid & 31;
    int wm = warp >> 1, wn = warp & 1;       // 4M x 2N
    int r4 = lane >> 2, c4 = lane & 3;
    int mrow = wm * 16;

    if (tid < 64) lrow[tid] = 0.f;

    // ---- prefetch: group1 = Q(h,l) + K(0); group2 = V(0) ----
    {
        #pragma unroll
        for (int i = 0; i < 4; i++) {
            int m = tid + i * 256;              // 1024: Qh 512 | Ql 512
            int r = (m & 511) >> 3, j = m & 7;
            if (m < 512)
                cp16(sb + OFF_QH + (uint32_t)(r * QKSB + j * 16), &g_Qh[p][i0 + r][j * 8]);
            else
                cp16(sb + OFF_QL + (uint32_t)(r * QKSB + j * 16), &g_Ql[p][i0 + r][j * 8]);
        }
        #pragma unroll
        for (int i = 0; i < 4; i++) {
            int m = tid + i * 256;              // 1024: Kh 512 | Kl 512
            int r = (m & 511) >> 3, j = m & 7;
            if (m < 512)
                cp16(sb + OFF_KH + (uint32_t)(r * QKSB + j * 16), &g_Kh[p][r][j * 8]);
            else
                cp16(sb + OFF_KL + (uint32_t)(r * QKSB + j * 16), &g_Kl[p][r][j * 8]);
        }
        CP_COMMIT();
        #pragma unroll
        for (int i = 0; i < 8; i++) {
            int m = tid + i * 256;              // 2048: 256 ch x 8
            int ch = m >> 3, j = m & 7;
            cp16(sb + OFF_V + (uint32_t)(ch * QKSB + j * 16), &g_V[p][ch][j * 8]);
        }
        CP_COMMIT();
    }

    float O[16][4];
    #pragma unroll
    for (int nt = 0; nt < 16; nt++)
        #pragma unroll
        for (int i = 0; i < 4; i++) O[nt][i] = 0.f;

    float lsum[2] = {};
    float m_run[2] = {-1e30f, -1e30f};

    for (int jt = 0; jt < 64; jt++) {
        CP_WAIT(1);
        __syncthreads();   // K(jt) (and Q on jt==0) ready

        // ---- S = QK^T: 3-term split-bf16; warp's 16 rows x 32 cols ----
        float cS[4][4];
        #pragma unroll
        for (int nt = 0; nt < 4; nt++)
            #pragma unroll
            for (int i = 0; i < 4; i++) cS[nt][i] = 0.f;

        #pragma unroll
        for (int kt = 0; kt < 4; kt++) {
            int kb = kt * 32 + c4 * 4;
            uint32_t ah[4], al[4];
            {
                int r = mrow + r4;
                const char* qh = smem + OFF_QH + r * QKSB + kb;
                const char* ql = smem + OFF_QL + r * QKSB + kb;
                ah[0] = *(const uint32_t*)qh;
                ah[1] = *(const uint32_t*)(qh + 8 * QKSB);
                ah[2] = *(const uint32_t*)(qh + 16);
                ah[3] = *(const uint32_t*)(qh + 8 * QKSB + 16);
                al[0] = *(const uint32_t*)ql;
                al[1] = *(const uint32_t*)(ql + 8 * QKSB);
                al[2] = *(const uint32_t*)(ql + 16);
                al[3] = *(const uint32_t*)(ql + 8 * QKSB + 16);
            }
            #pragma unroll
            for (int nt = 0; nt < 4; nt++) {
                int n = wn * 32 + nt * 8 + r4;
                const char* kh = smem + OFF_KH + n * QKSB + kb;
                const char* kl = smem + OFF_KL + n * QKSB + kb;
                uint32_t bh0 = *(const uint32_t*)kh;
                uint32_t bh1 = *(const uint32_t*)(kh + 16);
                uint32_t bl0 = *(const uint32_t*)kl;
                uint32_t bl1 = *(const uint32_t*)(kl + 16);
                mma16(cS[nt], ah, bh0, bh1);
                mma16(cS[nt], al, bh0, bh1);
                mma16(cS[nt], ah, bl0, bl1);
            }
        }

        // ---- warp-local partial row max over this warp's 32 cols ----
        {
            float m0 = -1e30f, m1 = -1e30f;
            #pragma unroll
            for (int nt = 0; nt < 4; nt++) {
                m0 = fmaxf(m0, fmaxf(cS[nt][0], cS[nt][1]));
                m1 = fmaxf(m1, fmaxf(cS[nt][2], cS[nt][3]));
            }
            m0 = fmaxf(m0, __shfl_xor_sync(0xffffffffu, m0, 1));
            m0 = fmaxf(m0, __shfl_xor_sync(0xffffffffu, m0, 2));
            m1 = fmaxf(m1, __shfl_xor_sync(0xffffffffu, m1, 1));
            m1 = fmaxf(m1, __shfl_xor_sync(0xffffffffu, m1, 2));
            if (c4 == 0) {
                int r = mrow + r4;
                pmax[wn * 64 + r]     = m0;
                pmax[wn * 64 + r + 8] = m1;
            }
        }
        __syncthreads();   // pmax visible; K smem consumed by all warps

        // ---- prefetch K(jt+1) early ----
        if (jt < 63) {
            int j0n = (jt + 1) << 6;
            #pragma unroll
            for (int i = 0; i < 4; i++) {
                int m = tid + i * 256;
                int r = (m & 511) >> 3, j = m & 7;
                if (m < 512)
                    cp16(sb + OFF_KH + (uint32_t)(r * QKSB + j * 16), &g_Kh[p][j0n + r][j * 8]);
                else
                    cp16(sb + OFF_KL + (uint32_t)(r * QKSB + j * 16), &g_Kl[p][j0n + r][j * 8]);
            }
            CP_COMMIT();
        }

        // ---- combined max, alpha, O-rescale, exp, pack fp16 P ----
        float m_new[2], alpha[2];
        #pragma unroll
        for (int h = 0; h < 2; h++) {
            int r = mrow + r4 + 8 * h;
            float mt_tile = fmaxf(pmax[r], pmax[64 + r]);
            m_new[h] = fmaxf(m_run[h], mt_tile);
            alpha[h] = __expf(m_run[h] - m_new[h]);
            m_run[h] = m_new[h];
        }
        bool anyr = (alpha[0] < 1.f) | (alpha[1] < 1.f);
        if (__any_sync(0xffffffffu, anyr)) {
            #pragma unroll
            for (int nt = 0; nt < 16; nt++) {
                O[nt][0] *= alpha[0];
                O[nt][1] *= alpha[0];
                O[nt][2] *= alpha[1];
                O[nt][3] *= alpha[1];
            }
        }

        {
            int r = mrow + r4;
            float s0 = 0.f, s1 = 0.f;
            #pragma unroll
            for (int nt = 0; nt < 4; nt++) {
                int col = wn * 32 + nt * 8 + 2 * c4;
                float e0 = __expf(cS[nt][0] - m_new[0]);
                float e1 = __expf(cS[nt][1] - m_new[0]);
                float e2 = __expf(cS[nt][2] - m_new[1]);
                float e3 = __expf(cS[nt][3] - m_new[1]);
                s0 += e0 + e1;
                s1 += e2 + e3;
                *(uint32_t*)(smem + OFF_P + r * QKSB + col * 2)       = pack_f16(e0, e1);
                *(uint32_t*)(smem + OFF_P + (r + 8) * QKSB + col * 2) = pack_f16(e2, e3);
            }
            lsum[0] = lsum[0] * alpha[0] + s0;
            lsum[1] = lsum[1] * alpha[1] + s1;
        }

        if (jt < 63) { CP_WAIT(1); } else { CP_WAIT(0); }
        __syncthreads();   // P visible; V(jt) ready

        // ---- O += P @ V^T (fp16); warp's 16 rows x 128 channels ----
        #pragma unroll
        for (int kt = 0; kt < 4; kt++) {
            int kb = kt * 32 + c4 * 4;
            uint32_t pa[4];
            {
                int r = mrow + r4;
                const char* pp = smem + OFF_P + r * QKSB + kb;
                pa[0] = *(const uint32_t*)pp;
                pa[1] = *(const uint32_t*)(pp + 8 * QKSB);
                pa[2] = *(const uint32_t*)(pp + 16);
                pa[3] = *(const uint32_t*)(pp + 8 * QKSB + 16);
            }
            #pragma unroll
            for (int nt = 0; nt < 16; nt++) {
                int ch = wn * 128 + nt * 8 + r4;
                const char* vv = smem + OFF_V + ch * QKSB + kb;
                uint32_t b0 = *(const uint32_t*)vv;
                uint32_t b1 = *(const uint32_t*)(vv + 16);
                mma16f(O[nt], pa, b0, b1);
            }
        }
        __syncthreads();   // V consumed

        // ---- prefetch V(jt+1) ----
        if (jt < 63) {
            int j0n = (jt + 1) << 6;
            #pragma unroll
            for (int i = 0; i < 8; i++) {
                int m = tid + i * 256;
                int ch = m >> 3, j = m & 7;
                cp16(sb + OFF_V + (uint32_t)(ch * QKSB + j * 16), &g_V[p][ch][j0n + j * 8]);
            }
            CP_COMMIT();
        }
    }

    // ---- row-sum reduction (across 2 N-warps) ----
    #pragma unroll
    for (int h = 0; h < 2; h++) {
        float v = lsum[h];
        v += __shfl_xor_sync(0xffffffffu, v, 1);
        v += __shfl_xor_sync(0xffffffffu, v, 2);
        if (c4 == 0) atomicAdd(&lrow[mrow + r4 + 8 * h], v);
    }
    __syncthreads();

    // ---- epilogue ----
    float gm = gamma[0];
    int s = p >> 1, b = p & 1;
    const float* xin = (s ? in2 : in1) + (size_t)b * CC * NPIX;
    float* o = out + (size_t)p * CC * NPIX;
    {
        int rlo = mrow + r4, rhi = rlo + 8;
        float sclo = gm / lrow[rlo];
        float schi = gm / lrow[rhi];
        size_t nlo = (size_t)(i0 + rlo), nhi = (size_t)(i0 + rhi);
        #pragma unroll
        for (int nt = 0; nt < 16; nt++) {
            int ch = wn * 128 + nt * 8 + 2 * c4;
            o[(size_t)ch * NPIX + nlo]       = O[nt][0] * sclo + xin[(size_t)ch * NPIX + nlo];
            o[(size_t)(ch + 1) * NPIX + nlo] = O[nt][1] * sclo + xin[(size_t)(ch + 1) * NPIX + nlo];
            o[(size_t)ch * NPIX + nhi]       = O[nt][2] * schi + xin[(size_t)ch * NPIX + nhi];
            o[(size_t)(ch + 1) * NPIX + nhi] = O[nt][3] * schi + xin[(size_t)(ch + 1) * NPIX + nhi];
        }
    }
}

// ---------------------------------------------------------------------------
extern "C" void kernel_launch(void* const* d_in, const int* in_sizes, int n_in,
                              void* d_out, int out_size)
{
    const float* in1 = (const float*)d_in[0];
    const float* in2 = (const float*)d_in[1];
    const float* q1w = (const float*)d_in[2];  const float* q1b = (const float*)d_in[3];
    const float* k1w = (const float*)d_in[4];  const float* k1b = (const float*)d_in[5];
    const float* v1w = (const float*)d_in[6];  const float* v1b = (const float*)d_in[7];
    const float* q2w = (const float*)d_in[8];  const float* q2b = (const float*)d_in[9];
    const float* k2w = (const float*)d_in[10]; const float* k2b = (const float*)d_in[11];
    const float* v2w = (const float*)d_in[12]; const float* v2b = (const float*)d_in[13];
    const float* gamma = (const float*)d_in[22];
    float* out = (float*)d_out;

    prep_weights<<<dim3(384, 2), 256>>>(q1w, q1b, k1w, k1b, v1w, v1b,
                                        q2w, q2b, k2w, k2b, v2w, v2b);
    convert_x<<<dim3(64, 4, 4), 256>>>(in1, in2);

    cudaFuncSetAttribute(proj_mma, cudaFuncAttributeMaxDynamicSharedMemorySize, (int)PSMEM);
    proj_mma<<<dim3(32, 3, 4), 256, PSMEM>>>();

    cudaFuncSetAttribute(flash_attn, cudaFuncAttributeMaxDynamicSharedMemorySize, (int)SMEM_TOTAL);
    flash_attn<<<dim3(64, 4), 256, SMEM_TOTAL>>>(in1, in2, gamma, out);
}

// round 11
// speedup vs baseline: 1.2183x; 1.2183x over previous
#include <cuda_runtime.h>
#include <cuda_bf16.h>
#include <cuda_fp16.h>
#include <cstdint>

#define CC    256
#define CQ    64
#define NPIX  4096
#define NPAIR 4

// ---------------- helpers ----------------
__device__ __forceinline__ uint32_t smem_u32(const void* p) {
    uint32_t a;
    asm("{ .reg .u64 t; cvta.to.shared.u64 t, %1; cvt.u32.u64 %0, t; }" : "=r"(a) : "l"(p));
    return a;
}

__device__ __forceinline__ void cp16(uint32_t s, const void* g) {
    asm volatile("cp.async.cg.shared.global [%0], [%1], 16;" :: "r"(s), "l"(g) : "memory");
}
#define CP_COMMIT()  asm volatile("cp.async.commit_group;" ::: "memory")
#define CP_WAIT(N)   asm volatile("cp.async.wait_group %0;" :: "n"(N) : "memory")

// ldmatrix x4: four 8x8 b16 matrices -> 4 regs (fragment order = address order)
__device__ __forceinline__ void ldsm4(uint32_t r[4], uint32_t addr) {
    asm volatile("ldmatrix.sync.aligned.m8n8.x4.shared.b16 {%0,%1,%2,%3}, [%4];"
        : "=r"(r[0]), "=r"(r[1]), "=r"(r[2]), "=r"(r[3]) : "r"(addr));
}

// m16n8k16 bf16 mma (S phase + proj)
__device__ __forceinline__ void mma16(float c[4], const uint32_t a[4], uint32_t b0, uint32_t b1) {
    asm volatile(
        "mma.sync.aligned.m16n8k16.row.col.f32.bf16.bf16.f32 "
        "{%0,%1,%2,%3}, {%4,%5,%6,%7}, {%8,%9}, {%0,%1,%2,%3};"
        : "+f"(c[0]), "+f"(c[1]), "+f"(c[2]), "+f"(c[3])
        : "r"(a[0]), "r"(a[1]), "r"(a[2]), "r"(a[3]), "r"(b0), "r"(b1));
}

// m16n8k16 fp16 mma (PV phase)
__device__ __forceinline__ void mma16f(float c[4], const uint32_t a[4], uint32_t b0, uint32_t b1) {
    asm volatile(
        "mma.sync.aligned.m16n8k16.row.col.f32.f16.f16.f32 "
        "{%0,%1,%2,%3}, {%4,%5,%6,%7}, {%8,%9}, {%0,%1,%2,%3};"
        : "+f"(c[0]), "+f"(c[1]), "+f"(c[2]), "+f"(c[3])
        : "r"(a[0]), "r"(a[1]), "r"(a[2]), "r"(a[3]), "r"(b0), "r"(b1));
}

__device__ __forceinline__ uint32_t pack_bf16(float a, float b) {
    __nv_bfloat16 h0 = __float2bfloat16(a), h1 = __float2bfloat16(b);
    uint16_t u0 = *(uint16_t*)&h0, u1 = *(uint16_t*)&h1;
    return ((uint32_t)u1 << 16) | u0;
}

__device__ __forceinline__ uint32_t pack_f16(float a, float b) {
    __half2 h = __floats2half2_rn(a, b);
    return *(uint32_t*)&h;
}

// ---------------- scratch ----------------
__device__ float g_Bias[2][384];
__device__ __nv_bfloat16 g_Wh[2][384][CC];
__device__ __nv_bfloat16 g_Wl[2][384][CC];
__device__ __nv_bfloat16 g_Xh[NPAIR][NPIX][CC];
__device__ __nv_bfloat16 g_Xl[NPAIR][NPIX][CC];
__device__ __nv_bfloat16 g_Qh[NPAIR][NPIX][CQ];
__device__ __nv_bfloat16 g_Ql[NPAIR][NPIX][CQ];
__device__ __nv_bfloat16 g_Kh[NPAIR][NPIX][CQ];
__device__ __nv_bfloat16 g_Kl[NPAIR][NPIX][CQ];
__device__ __half g_V[NPAIR][CC][NPIX];          // channel-major fp16 V

// ---------------------------------------------------------------------------
__global__ void prep_weights(
    const float* __restrict__ q1w, const float* __restrict__ q1b,
    const float* __restrict__ k1w, const float* __restrict__ k1b,
    const float* __restrict__ v1w, const float* __restrict__ v1b,
    const float* __restrict__ q2w, const float* __restrict__ q2b,
    const float* __restrict__ k2w, const float* __restrict__ k2b,
    const float* __restrict__ v2w, const float* __restrict__ v2b)
{
    int o = blockIdx.x, s = blockIdx.y;
    const float* w; const float* bsrc; int row;
    if (o < 64)       { w = s ? q2w : q1w; bsrc = s ? q2b : q1b; row = o; }
    else if (o < 128) { w = s ? k2w : k1w; bsrc = s ? k2b : k1b; row = o - 64; }
    else              { w = s ? v2w : v1w; bsrc = s ? v2b : v1b; row = o - 128; }
    float v = w[row * CC + threadIdx.x];
    __nv_bfloat16 h = __float2bfloat16(v);
    g_Wh[s][o][threadIdx.x] = h;
    g_Wl[s][o][threadIdx.x] = __float2bfloat16(v - __bfloat162float(h));
    if (threadIdx.x == 0) g_Bias[s][o] = bsrc[row];
}

// ---------------------------------------------------------------------------
__global__ __launch_bounds__(256) void convert_x(
    const float* __restrict__ in1, const float* __restrict__ in2)
{
    __shared__ float t[64][65];
    int p = blockIdx.z, s = p >> 1, b = p & 1;
    const float* x = (s ? in2 : in1) + (size_t)b * CC * NPIX;
    int n0 = blockIdx.x * 64, c0 = blockIdx.y * 64;
    int tid = threadIdx.x;

    #pragma unroll
    for (int i = 0; i < 4; i++) {
        int m = tid + i * 256;
        int c = m >> 4, nn = (m & 15) << 2;
        float4 v = *(const float4*)&x[(size_t)(c0 + c) * NPIX + n0 + nn];
        t[c][nn] = v.x; t[c][nn + 1] = v.y; t[c][nn + 2] = v.z; t[c][nn + 3] = v.w;
    }
    __syncthreads();

    int n = tid >> 2, cb = (tid & 3) << 4;
    uint32_t hw[8], lw[8];
    #pragma unroll
    for (int j = 0; j < 8; j++) {
        float v0 = t[cb + 2 * j][n], v1 = t[cb + 2 * j + 1][n];
        __nv_bfloat16 h0 = __float2bfloat16(v0);
        __nv_bfloat16 h1 = __float2bfloat16(v1);
        float l0 = v0 - __bfloat162float(h0);
        float l1 = v1 - __bfloat162float(h1);
        uint16_t a0 = *(uint16_t*)&h0, a1 = *(uint16_t*)&h1;
        hw[j] = ((uint32_t)a1 << 16) | a0;
        lw[j] = pack_bf16(l0, l1);
    }
    uint4* dh = (uint4*)&g_Xh[p][n0 + n][c0 + cb];
    uint4* dl = (uint4*)&g_Xl[p][n0 + n][c0 + cb];
    dh[0] = make_uint4(hw[0], hw[1], hw[2], hw[3]);
    dh[1] = make_uint4(hw[4], hw[5], hw[6], hw[7]);
    dl[0] = make_uint4(lw[0], lw[1], lw[2], lw[3]);
    dl[1] = make_uint4(lw[4], lw[5], lw[6], lw[7]);
}

// ---------------------------------------------------------------------------
// Tensorized projection (unchanged)
// ---------------------------------------------------------------------------
#define PJS 144u
#define PA_H 0u
#define PA_L 18432u
#define PB_H 36864u
#define PB_L 55296u
#define PSTAGE 73728u
#define POFF_BIAS 147456u
#define PSMEM 147968u

__global__ __launch_bounds__(256, 1) void proj_mma()
{
    extern __shared__ __align__(16) char psm[];
    uint32_t sb = smem_u32(psm);
    float* bias = (float*)(psm + POFF_BIAS);
    int tid = threadIdx.x;
    int p = blockIdx.z, s = p >> 1;
    int n0 = blockIdx.x * 128, o0 = blockIdx.y * 128;
    int warp = tid >> 5, lane = tid & 31;
    int wm = warp >> 1, wn = warp & 1;
    int r4 = lane >> 2, c4 = lane & 3;

    if (tid < 128) bias[tid] = g_Bias[s][o0 + tid];

    auto issue = [&](int kc) {
        uint32_t st = sb + (uint32_t)(kc & 1) * PSTAGE;
        int k0 = kc * 64;
        #pragma unroll
        for (int i = 0; i < 4; i++) {
            int m = tid + i * 256;
            int r = m >> 3, j = m & 7;
            uint32_t off = (uint32_t)r * PJS + (uint32_t)j * 16u;
            cp16(st + PA_H + off, &g_Xh[p][n0 + r][k0 + j * 8]);
            cp16(st + PA_L + off, &g_Xl[p][n0 + r][k0 + j * 8]);
            cp16(st + PB_H + off, &g_Wh[s][o0 + r][k0 + j * 8]);
            cp16(st + PB_L + off, &g_Wl[s][o0 + r][k0 + j * 8]);
        }
        CP_COMMIT();
    };
    issue(0);
    issue(1);

    float cS[2][8][4] = {};

    for (int kc = 0; kc < 4; kc++) {
        CP_WAIT(1);
        __syncthreads();
        const char* st = psm + (kc & 1) * PSTAGE;

        #pragma unroll
        for (int kt = 0; kt < 4; kt++) {
            int kb = kt * 32 + c4 * 4;
            uint32_t ah[2][4], al[2][4];
            #pragma unroll
            for (int mt = 0; mt < 2; mt++) {
                int r = wm * 32 + mt * 16 + r4;
                const char* a_h = st + PA_H + r * PJS + kb;
                const char* a_l = st + PA_L + r * PJS + kb;
                ah[mt][0] = *(const uint32_t*)a_h;
                ah[mt][1] = *(const uint32_t*)(a_h + 8 * PJS);
                ah[mt][2] = *(const uint32_t*)(a_h + 16);
                ah[mt][3] = *(const uint32_t*)(a_h + 8 * PJS + 16);
                al[mt][0] = *(const uint32_t*)a_l;
                al[mt][1] = *(const uint32_t*)(a_l + 8 * PJS);
                al[mt][2] = *(const uint32_t*)(a_l + 16);
                al[mt][3] = *(const uint32_t*)(a_l + 8 * PJS + 16);
            }
            #pragma unroll
            for (int nt = 0; nt < 8; nt++) {
                int o = wn * 64 + nt * 8 + r4;
                const char* b_h = st + PB_H + o * PJS + kb;
                const char* b_l = st + PB_L + o * PJS + kb;
                uint32_t bh0 = *(const uint32_t*)b_h;
                uint32_t bh1 = *(const uint32_t*)(b_h + 16);
                uint32_t bl0 = *(const uint32_t*)b_l;
                uint32_t bl1 = *(const uint32_t*)(b_l + 16);
                #pragma unroll
                for (int mt = 0; mt < 2; mt++) {
                    mma16(cS[mt][nt], ah[mt], bh0, bh1);
                    mma16(cS[mt][nt], al[mt], bh0, bh1);
                    mma16(cS[mt][nt], ah[mt], bl0, bl1);
                }
            }
        }
        __syncthreads();
        if (kc < 2) issue(kc + 2);
    }

    #pragma unroll
    for (int mt = 0; mt < 2; mt++) {
        int n_lo = n0 + wm * 32 + mt * 16 + r4;
        int n_hi = n_lo + 8;
        #pragma unroll
        for (int nt = 0; nt < 8; nt++) {
            int ol = wn * 64 + nt * 8 + 2 * c4;
            int og = o0 + ol;
            float b0 = bias[ol], b1 = bias[ol + 1];
            float y00 = cS[mt][nt][0] + b0, y01 = cS[mt][nt][1] + b1;
            float y10 = cS[mt][nt][2] + b0, y11 = cS[mt][nt][3] + b1;
            if (og < 64) {
                __nv_bfloat16 h00 = __float2bfloat16(y00), h01 = __float2bfloat16(y01);
                __nv_bfloat16 h10 = __float2bfloat16(y10), h11 = __float2bfloat16(y11);
                uint16_t u00 = *(uint16_t*)&h00, u01 = *(uint16_t*)&h01;
                uint16_t u10 = *(uint16_t*)&h10, u11 = *(uint16_t*)&h11;
                *(uint32_t*)&g_Qh[p][n_lo][og] = ((uint32_t)u01 << 16) | u00;
                *(uint32_t*)&g_Qh[p][n_hi][og] = ((uint32_t)u11 << 16) | u10;
                *(uint32_t*)&g_Ql[p][n_lo][og] =
                    pack_bf16(y00 - __bfloat162float(h00), y01 - __bfloat162float(h01));
                *(uint32_t*)&g_Ql[p][n_hi][og] =
                    pack_bf16(y10 - __bfloat162float(h10), y11 - __bfloat162float(h11));
            } else if (og < 128) {
                int oo = og - 64;
                __nv_bfloat16 h00 = __float2bfloat16(y00), h01 = __float2bfloat16(y01);
                __nv_bfloat16 h10 = __float2bfloat16(y10), h11 = __float2bfloat16(y11);
                uint16_t u00 = *(uint16_t*)&h00, u01 = *(uint16_t*)&h01;
                uint16_t u10 = *(uint16_t*)&h10, u11 = *(uint16_t*)&h11;
                *(uint32_t*)&g_Kh[p][n_lo][oo] = ((uint32_t)u01 << 16) | u00;
                *(uint32_t*)&g_Kh[p][n_hi][oo] = ((uint32_t)u11 << 16) | u10;
                *(uint32_t*)&g_Kl[p][n_lo][oo] =
                    pack_bf16(y00 - __bfloat162float(h00), y01 - __bfloat162float(h01));
                *(uint32_t*)&g_Kl[p][n_hi][oo] =
                    pack_bf16(y10 - __bfloat162float(h10), y11 - __bfloat162float(h11));
            } else {
                int c = og - 128;
                g_V[p][c][n_lo]     = __float2half(y00);
                g_V[p][c + 1][n_lo] = __float2half(y01);
                g_V[p][c][n_hi]     = __float2half(y10);
                g_V[p][c + 1][n_hi] = __float2half(y11);
            }
        }
    }
}

// ---------------------------------------------------------------------------
// Flash attention: R8 shape (128-row tiles, 8 warps 4M x 2N, 1 CTA/SM),
// fragment loads via ldmatrix.x4. S bf16 3-term; PV fp16; online row max.
// ---------------------------------------------------------------------------
#define QKSB 144
#define OFF_QH 0u
#define OFF_QL (OFF_QH + 128u * QKSB)
#define OFF_KH (OFF_QL + 128u * QKSB)
#define OFF_KL (OFF_KH + 64u * QKSB)
#define OFF_V  (OFF_KL + 64u * QKSB)               // 256 ch x 144B (fp16)
#define OFF_P  (OFF_V + 256u * QKSB)               // 128 rows x 144B (fp16)
#define OFF_L  (OFF_P + 128u * QKSB)               // lrow: 128 f32
#define OFF_PM (OFF_L + 512u)                      // pmax: 2 x 128 f32
#define SMEM_TOTAL (OFF_PM + 1024u)

__global__ __launch_bounds__(256, 1)
void flash_attn(const float* __restrict__ in1, const float* __restrict__ in2,
                const float* __restrict__ gamma, float* __restrict__ out)
{
    extern __shared__ __align__(16) char smem[];
    float* lrow = (float*)(smem + OFF_L);
    float* pmax = (float*)(smem + OFF_PM);
    uint32_t sb = smem_u32(smem);

    int tid  = threadIdx.x;
    int p    = blockIdx.y;
    int i0   = blockIdx.x * 128;
    int warp = tid >> 5, lane = tid & 31;
    int wm = warp >> 1, wn = warp & 1;       // 4M x 2N
    int r4 = lane >> 2, c4 = lane & 3;
    int lm = lane >> 3, lr = lane & 7;       // ldmatrix: matrix id, row-in-matrix
    int mrow = wm * 32;

    // ldmatrix lane-address components:
    // A-style (Q,P): row = rowbase + (lm&1)*8 + lr ; kbyte += (lm>>1)*16
    // B-style (K,V): row = nbase  + (lm>>1)*8 + lr ; kbyte += (lm&1)*16
    uint32_t aRow = (uint32_t)((lm & 1) * 8 + lr) * QKSB + (uint32_t)((lm >> 1) * 16);
    uint32_t bRow = (uint32_t)((lm >> 1) * 8 + lr) * QKSB + (uint32_t)((lm & 1) * 16);

    if (tid < 128) lrow[tid] = 0.f;

    // ---- prefetch: group1 = Q(h,l) + K(0); group2 = V(0) ----
    {
        #pragma unroll
        for (int i = 0; i < 8; i++) {
            int m = tid + i * 256;
            int r = (m & 1023) >> 3, j = m & 7;
            if (m < 1024)
                cp16(sb + OFF_QH + (uint32_t)(r * QKSB + j * 16), &g_Qh[p][i0 + r][j * 8]);
            else
                cp16(sb + OFF_QL + (uint32_t)(r * QKSB + j * 16), &g_Ql[p][i0 + r][j * 8]);
        }
        #pragma unroll
        for (int i = 0; i < 4; i++) {
            int m = tid + i * 256;
            int r = (m & 511) >> 3, j = m & 7;
            if (m < 512)
                cp16(sb + OFF_KH + (uint32_t)(r * QKSB + j * 16), &g_Kh[p][r][j * 8]);
            else
                cp16(sb + OFF_KL + (uint32_t)(r * QKSB + j * 16), &g_Kl[p][r][j * 8]);
        }
        CP_COMMIT();
        #pragma unroll
        for (int i = 0; i < 8; i++) {
            int m = tid + i * 256;
            int ch = m >> 3, j = m & 7;
            cp16(sb + OFF_V + (uint32_t)(ch * QKSB + j * 16), &g_V[p][ch][j * 8]);
        }
        CP_COMMIT();
    }

    float O[2][16][4];
    #pragma unroll
    for (int mt = 0; mt < 2; mt++)
        #pragma unroll
        for (int nt = 0; nt < 16; nt++)
            #pragma unroll
            for (int i = 0; i < 4; i++) O[mt][nt][i] = 0.f;

    float lsum[2][2] = {};
    float m_run[2][2] = {{-1e30f, -1e30f}, {-1e30f, -1e30f}};

    for (int jt = 0; jt < 64; jt++) {
        CP_WAIT(1);
        __syncthreads();   // K(jt) (and Q on jt==0) ready

        // ---- S = QK^T: 3-term split-bf16, fragments via ldmatrix ----
        float cS[2][4][4];
        #pragma unroll
        for (int mt = 0; mt < 2; mt++)
            #pragma unroll
            for (int nt = 0; nt < 4; nt++)
                #pragma unroll
                for (int i = 0; i < 4; i++) cS[mt][nt][i] = 0.f;

        #pragma unroll
        for (int kt = 0; kt < 4; kt++) {
            uint32_t kbyte = (uint32_t)kt * 32u;
            uint32_t ah[2][4], al[2][4];
            #pragma unroll
            for (int mt = 0; mt < 2; mt++) {
                uint32_t qaddr = sb + OFF_QH + (uint32_t)(mrow + mt * 16) * QKSB + kbyte + aRow;
                ldsm4(ah[mt], qaddr);
                ldsm4(al[mt], qaddr + (OFF_QL - OFF_QH));
            }
            #pragma unroll
            for (int ntp = 0; ntp < 2; ntp++) {
                uint32_t kaddr = sb + OFF_KH + (uint32_t)(wn * 32 + ntp * 16) * QKSB + kbyte + bRow;
                uint32_t bh[4], bl[4];
                ldsm4(bh, kaddr);
                ldsm4(bl, kaddr + (OFF_KL - OFF_KH));
                #pragma unroll
                for (int mt = 0; mt < 2; mt++) {
                    mma16(cS[mt][2 * ntp],     ah[mt], bh[0], bh[1]);
                    mma16(cS[mt][2 * ntp],     al[mt], bh[0], bh[1]);
                    mma16(cS[mt][2 * ntp],     ah[mt], bl[0], bl[1]);
                    mma16(cS[mt][2 * ntp + 1], ah[mt], bh[2], bh[3]);
                    mma16(cS[mt][2 * ntp + 1], al[mt], bh[2], bh[3]);
                    mma16(cS[mt][2 * ntp + 1], ah[mt], bl[2], bl[3]);
                }
            }
        }

        // ---- warp-local partial row max over this warp's 32 cols ----
        float pm[2][2];
        #pragma unroll
        for (int mt = 0; mt < 2; mt++) {
            float m0 = -1e30f, m1 = -1e30f;
            #pragma unroll
            for (int nt = 0; nt < 4; nt++) {
                m0 = fmaxf(m0, fmaxf(cS[mt][nt][0], cS[mt][nt][1]));
                m1 = fmaxf(m1, fmaxf(cS[mt][nt][2], cS[mt][nt][3]));
            }
            m0 = fmaxf(m0, __shfl_xor_sync(0xffffffffu, m0, 1));
            m0 = fmaxf(m0, __shfl_xor_sync(0xffffffffu, m0, 2));
            m1 = fmaxf(m1, __shfl_xor_sync(0xffffffffu, m1, 1));
            m1 = fmaxf(m1, __shfl_xor_sync(0xffffffffu, m1, 2));
            pm[mt][0] = m0; pm[mt][1] = m1;
        }
        if (c4 == 0) {
            #pragma unroll
            for (int mt = 0; mt < 2; mt++) {
                int r = mrow + mt * 16 + r4;
                pmax[wn * 128 + r]     = pm[mt][0];
                pmax[wn * 128 + r + 8] = pm[mt][1];
            }
        }
        __syncthreads();   // pmax visible; K smem consumed by all warps

        // ---- prefetch K(jt+1) early (overlaps with softmax below) ----
        if (jt < 63) {
            int j0n = (jt + 1) << 6;
            #pragma unroll
            for (int i = 0; i < 4; i++) {
                int m = tid + i * 256;
                int r = (m & 511) >> 3, j = m & 7;
                if (m < 512)
                    cp16(sb + OFF_KH + (uint32_t)(r * QKSB + j * 16), &g_Kh[p][j0n + r][j * 8]);
                else
                    cp16(sb + OFF_KL + (uint32_t)(r * QKSB + j * 16), &g_Kl[p][j0n + r][j * 8]);
            }
            CP_COMMIT();
        }

        // ---- combined max, alpha, O-rescale, exp, pack fp16 P ----
        float m_new[2][2], alpha[2][2];
        #pragma unroll
        for (int mt = 0; mt < 2; mt++) {
            #pragma unroll
            for (int h = 0; h < 2; h++) {
                int r = mrow + mt * 16 + r4 + 8 * h;
                float mt_tile = fmaxf(pmax[r], pmax[128 + r]);
                m_new[mt][h] = fmaxf(m_run[mt][h], mt_tile);
                alpha[mt][h] = __expf(m_run[mt][h] - m_new[mt][h]);
                m_run[mt][h] = m_new[mt][h];
            }
        }
        bool anyr = (alpha[0][0] < 1.f) | (alpha[0][1] < 1.f)
                  | (alpha[1][0] < 1.f) | (alpha[1][1] < 1.f);
        if (__any_sync(0xffffffffu, anyr)) {
            #pragma unroll
            for (int mt = 0; mt < 2; mt++)
                #pragma unroll
                for (int nt = 0; nt < 16; nt++) {
                    O[mt][nt][0] *= alpha[mt][0];
                    O[mt][nt][1] *= alpha[mt][0];
                    O[mt][nt][2] *= alpha[mt][1];
                    O[mt][nt][3] *= alpha[mt][1];
                }
        }

        #pragma unroll
        for (int mt = 0; mt < 2; mt++) {
            int r = mrow + mt * 16 + r4;
            float s0 = 0.f, s1 = 0.f;
            #pragma unroll
            for (int nt = 0; nt < 4; nt++) {
                int col = wn * 32 + nt * 8 + 2 * c4;
                float e0 = __expf(cS[mt][nt][0] - m_new[mt][0]);
                float e1 = __expf(cS[mt][nt][1] - m_new[mt][0]);
                float e2 = __expf(cS[mt][nt][2] - m_new[mt][1]);
                float e3 = __expf(cS[mt][nt][3] - m_new[mt][1]);
                s0 += e0 + e1;
                s1 += e2 + e3;
                *(uint32_t*)(smem + OFF_P + r * QKSB + col * 2)       = pack_f16(e0, e1);
                *(uint32_t*)(smem + OFF_P + (r + 8) * QKSB + col * 2) = pack_f16(e2, e3);
            }
            lsum[mt][0] = lsum[mt][0] * alpha[mt][0] + s0;
            lsum[mt][1] = lsum[mt][1] * alpha[mt][1] + s1;
        }

        if (jt < 63) { CP_WAIT(1); } else { CP_WAIT(0); }
        __syncthreads();   // P visible; V(jt) ready

        // ---- O += P @ V^T (fp16), fragments via ldmatrix ----
        #pragma unroll
        for (int kt = 0; kt < 4; kt++) {
            uint32_t kbyte = (uint32_t)kt * 32u;
            uint32_t pa[2][4];
            #pragma unroll
            for (int mt = 0; mt < 2; mt++) {
                uint32_t paddr = sb + OFF_P + (uint32_t)(mrow + mt * 16) * QKSB + kbyte + aRow;
                ldsm4(pa[mt], paddr);
            }
            #pragma unroll
            for (int ntp = 0; ntp < 8; ntp++) {
                uint32_t vaddr = sb + OFF_V + (uint32_t)(wn * 128 + ntp * 16) * QKSB + kbyte + bRow;
                uint32_t vb[4];
                ldsm4(vb, vaddr);
                mma16f(O[0][2 * ntp],     pa[0], vb[0], vb[1]);
                mma16f(O[1][2 * ntp],     pa[1], vb[0], vb[1]);
                mma16f(O[0][2 * ntp + 1], pa[0], vb[2], vb[3]);
                mma16f(O[1][2 * ntp + 1], pa[1], vb[2], vb[3]);
            }
        }
        __syncthreads();   // V consumed

        // ---- prefetch V(jt+1) ----
        if (jt < 63) {
            int j0n = (jt + 1) << 6;
            #pragma unroll
            for (int i = 0; i < 8; i++) {
                int m = tid + i * 256;
                int ch = m >> 3, j = m & 7;
                cp16(sb + OFF_V + (uint32_t)(ch * QKSB + j * 16), &g_V[p][ch][j0n + j * 8]);
            }
            CP_COMMIT();
        }
    }

    // ---- row-sum reduction ----
    #pragma unroll
    for (int mt = 0; mt < 2; mt++)
        #pragma unroll
        for (int h = 0; h < 2; h++) {
            float v = lsum[mt][h];
            v += __shfl_xor_sync(0xffffffffu, v, 1);
            v += __shfl_xor_sync(0xffffffffu, v, 2);
            if (c4 == 0) atomicAdd(&lrow[mrow + mt * 16 + r4 + 8 * h], v);
        }
    __syncthreads();

    // ---- epilogue ----
    float gm = gamma[0];
    int s = p >> 1, b = p & 1;
    const float* xin = (s ? in2 : in1) + (size_t)b * CC * NPIX;
    float* o = out + (size_t)p * CC * NPIX;
    #pragma unroll
    for (int mt = 0; mt < 2; mt++) {
        int rlo = mrow + mt * 16 + r4, rhi = rlo + 8;
        float sclo = gm / lrow[rlo];
        float schi = gm / lrow[rhi];
        size_t nlo = (size_t)(i0 + rlo), nhi = (size_t)(i0 + rhi);
        #pragma unroll
        for (int nt = 0; nt < 16; nt++) {
            int ch = wn * 128 + nt * 8 + 2 * c4;
            o[(size_t)ch * NPIX + nlo]       = O[mt][nt][0] * sclo + xin[(size_t)ch * NPIX + nlo];
            o[(size_t)(ch + 1) * NPIX + nlo] = O[mt][nt][1] * sclo + xin[(size_t)(ch + 1) * NPIX + nlo];
            o[(size_t)ch * NPIX + nhi]       = O[mt][nt][2] * schi + xin[(size_t)ch * NPIX + nhi];
            o[(size_t)(ch + 1) * NPIX + nhi] = O[mt][nt][3] * schi + xin[(size_t)(ch + 1) * NPIX + nhi];
        }
    }
}

// ---------------------------------------------------------------------------
extern "C" void kernel_launch(void* const* d_in, const int* in_sizes, int n_in,
                              void* d_out, int out_size)
{
    const float* in1 = (const float*)d_in[0];
    const float* in2 = (const float*)d_in[1];
    const float* q1w = (const float*)d_in[2];  const float* q1b = (const float*)d_in[3];
    const float* k1w = (const float*)d_in[4];  const float* k1b = (const float*)d_in[5];
    const float* v1w = (const float*)d_in[6];  const float* v1b = (const float*)d_in[7];
    const float* q2w = (const float*)d_in[8];  const float* q2b = (const float*)d_in[9];
    const float* k2w = (const float*)d_in[10]; const float* k2b = (const float*)d_in[11];
    const float* v2w = (const float*)d_in[12]; const float* v2b = (const float*)d_in[13];
    const float* gamma = (const float*)d_in[22];
    float* out = (float*)d_out;

    prep_weights<<<dim3(384, 2), 256>>>(q1w, q1b, k1w, k1b, v1w, v1b,
                                        q2w, q2b, k2w, k2b, v2w, v2b);
    convert_x<<<dim3(64, 4, 4), 256>>>(in1, in2);

    cudaFuncSetAttribute(proj_mma, cudaFuncAttributeMaxDynamicSharedMemorySize, (int)PSMEM);
    proj_mma<<<dim3(32, 3, 4), 256, PSMEM>>>();

    cudaFuncSetAttribute(flash_attn, cudaFuncAttributeMaxDynamicSharedMemorySize, (int)SMEM_TOTAL);
    flash_attn<<<dim3(32, 4), 256, SMEM_TOTAL>>>(in1, in2, gamma, out);
}

// round 12
// speedup vs baseline: 1.2402x; 1.0179x over previous
#include <cuda_runtime.h>
#include <cuda_bf16.h>
#include <cuda_fp16.h>
#include <cstdint>

#define CC    256
#define CQ    64
#define NPIX  4096
#define NPAIR 4

// ---------------- helpers ----------------
__device__ __forceinline__ uint32_t smem_u32(const void* p) {
    uint32_t a;
    asm("{ .reg .u64 t; cvta.to.shared.u64 t, %1; cvt.u32.u64 %0, t; }" : "=r"(a) : "l"(p));
    return a;
}

__device__ __forceinline__ void cp16(uint32_t s, const void* g) {
    asm volatile("cp.async.cg.shared.global [%0], [%1], 16;" :: "r"(s), "l"(g) : "memory");
}
#define CP_COMMIT()  asm volatile("cp.async.commit_group;" ::: "memory")
#define CP_WAIT(N)   asm volatile("cp.async.wait_group %0;" :: "n"(N) : "memory")

// ldmatrix x4: four 8x8 b16 matrices -> 4 regs
__device__ __forceinline__ void ldsm4(uint32_t r[4], uint32_t addr) {
    asm volatile("ldmatrix.sync.aligned.m8n8.x4.shared.b16 {%0,%1,%2,%3}, [%4];"
        : "=r"(r[0]), "=r"(r[1]), "=r"(r[2]), "=r"(r[3]) : "r"(addr));
}

// m16n8k16 bf16 mma (S phase + proj)
__device__ __forceinline__ void mma16(float c[4], const uint32_t a[4], uint32_t b0, uint32_t b1) {
    asm volatile(
        "mma.sync.aligned.m16n8k16.row.col.f32.bf16.bf16.f32 "
        "{%0,%1,%2,%3}, {%4,%5,%6,%7}, {%8,%9}, {%0,%1,%2,%3};"
        : "+f"(c[0]), "+f"(c[1]), "+f"(c[2]), "+f"(c[3])
        : "r"(a[0]), "r"(a[1]), "r"(a[2]), "r"(a[3]), "r"(b0), "r"(b1));
}

// m16n8k16 fp16 mma (PV phase)
__device__ __forceinline__ void mma16f(float c[4], const uint32_t a[4], uint32_t b0, uint32_t b1) {
    asm volatile(
        "mma.sync.aligned.m16n8k16.row.col.f32.f16.f16.f32 "
        "{%0,%1,%2,%3}, {%4,%5,%6,%7}, {%8,%9}, {%0,%1,%2,%3};"
        : "+f"(c[0]), "+f"(c[1]), "+f"(c[2]), "+f"(c[3])
        : "r"(a[0]), "r"(a[1]), "r"(a[2]), "r"(a[3]), "r"(b0), "r"(b1));
}

__device__ __forceinline__ uint32_t pack_bf16(float a, float b) {
    __nv_bfloat16 h0 = __float2bfloat16(a), h1 = __float2bfloat16(b);
    uint16_t u0 = *(uint16_t*)&h0, u1 = *(uint16_t*)&h1;
    return ((uint32_t)u1 << 16) | u0;
}

__device__ __forceinline__ uint32_t pack_f16(float a, float b) {
    __half2 h = __floats2half2_rn(a, b);
    return *(uint32_t*)&h;
}

// ---------------- scratch ----------------
__device__ float g_Bias[2][384];
__device__ __nv_bfloat16 g_Wh[2][384][CC];
__device__ __nv_bfloat16 g_Wl[2][384][CC];
__device__ __nv_bfloat16 g_Xh[NPAIR][NPIX][CC];
__device__ __nv_bfloat16 g_Xl[NPAIR][NPIX][CC];
__device__ __nv_bfloat16 g_Qh[NPAIR][NPIX][CQ];
__device__ __nv_bfloat16 g_Ql[NPAIR][NPIX][CQ];
__device__ __nv_bfloat16 g_Kh[NPAIR][NPIX][CQ];
__device__ __nv_bfloat16 g_Kl[NPAIR][NPIX][CQ];
__device__ __half g_V[NPAIR][CC][NPIX];          // channel-major fp16 V

// ---------------------------------------------------------------------------
__global__ void prep_weights(
    const float* __restrict__ q1w, const float* __restrict__ q1b,
    const float* __restrict__ k1w, const float* __restrict__ k1b,
    const float* __restrict__ v1w, const float* __restrict__ v1b,
    const float* __restrict__ q2w, const float* __restrict__ q2b,
    const float* __restrict__ k2w, const float* __restrict__ k2b,
    const float* __restrict__ v2w, const float* __restrict__ v2b)
{
    int o = blockIdx.x, s = blockIdx.y;
    const float* w; const float* bsrc; int row;
    if (o < 64)       { w = s ? q2w : q1w; bsrc = s ? q2b : q1b; row = o; }
    else if (o < 128) { w = s ? k2w : k1w; bsrc = s ? k2b : k1b; row = o - 64; }
    else              { w = s ? v2w : v1w; bsrc = s ? v2b : v1b; row = o - 128; }
    float v = w[row * CC + threadIdx.x];
    __nv_bfloat16 h = __float2bfloat16(v);
    g_Wh[s][o][threadIdx.x] = h;
    g_Wl[s][o][threadIdx.x] = __float2bfloat16(v - __bfloat162float(h));
    if (threadIdx.x == 0) g_Bias[s][o] = bsrc[row];
}

// ---------------------------------------------------------------------------
__global__ __launch_bounds__(256) void convert_x(
    const float* __restrict__ in1, const float* __restrict__ in2)
{
    __shared__ float t[64][65];
    int p = blockIdx.z, s = p >> 1, b = p & 1;
    const float* x = (s ? in2 : in1) + (size_t)b * CC * NPIX;
    int n0 = blockIdx.x * 64, c0 = blockIdx.y * 64;
    int tid = threadIdx.x;

    #pragma unroll
    for (int i = 0; i < 4; i++) {
        int m = tid + i * 256;
        int c = m >> 4, nn = (m & 15) << 2;
        float4 v = *(const float4*)&x[(size_t)(c0 + c) * NPIX + n0 + nn];
        t[c][nn] = v.x; t[c][nn + 1] = v.y; t[c][nn + 2] = v.z; t[c][nn + 3] = v.w;
    }
    __syncthreads();

    int n = tid >> 2, cb = (tid & 3) << 4;
    uint32_t hw[8], lw[8];
    #pragma unroll
    for (int j = 0; j < 8; j++) {
        float v0 = t[cb + 2 * j][n], v1 = t[cb + 2 * j + 1][n];
        __nv_bfloat16 h0 = __float2bfloat16(v0);
        __nv_bfloat16 h1 = __float2bfloat16(v1);
        float l0 = v0 - __bfloat162float(h0);
        float l1 = v1 - __bfloat162float(h1);
        uint16_t a0 = *(uint16_t*)&h0, a1 = *(uint16_t*)&h1;
        hw[j] = ((uint32_t)a1 << 16) | a0;
        lw[j] = pack_bf16(l0, l1);
    }
    uint4* dh = (uint4*)&g_Xh[p][n0 + n][c0 + cb];
    uint4* dl = (uint4*)&g_Xl[p][n0 + n][c0 + cb];
    dh[0] = make_uint4(hw[0], hw[1], hw[2], hw[3]);
    dh[1] = make_uint4(hw[4], hw[5], hw[6], hw[7]);
    dl[0] = make_uint4(lw[0], lw[1], lw[2], lw[3]);
    dl[1] = make_uint4(lw[4], lw[5], lw[6], lw[7]);
}

// ---------------------------------------------------------------------------
// Tensorized projection (unchanged)
// ---------------------------------------------------------------------------
#define PJS 144u
#define PA_H 0u
#define PA_L 18432u
#define PB_H 36864u
#define PB_L 55296u
#define PSTAGE 73728u
#define POFF_BIAS 147456u
#define PSMEM 147968u

__global__ __launch_bounds__(256, 1) void proj_mma()
{
    extern __shared__ __align__(16) char psm[];
    uint32_t sb = smem_u32(psm);
    float* bias = (float*)(psm + POFF_BIAS);
    int tid = threadIdx.x;
    int p = blockIdx.z, s = p >> 1;
    int n0 = blockIdx.x * 128, o0 = blockIdx.y * 128;
    int warp = tid >> 5, lane = tid & 31;
    int wm = warp >> 1, wn = warp & 1;
    int r4 = lane >> 2, c4 = lane & 3;

    if (tid < 128) bias[tid] = g_Bias[s][o0 + tid];

    auto issue = [&](int kc) {
        uint32_t st = sb + (uint32_t)(kc & 1) * PSTAGE;
        int k0 = kc * 64;
        #pragma unroll
        for (int i = 0; i < 4; i++) {
            int m = tid + i * 256;
            int r = m >> 3, j = m & 7;
            uint32_t off = (uint32_t)r * PJS + (uint32_t)j * 16u;
            cp16(st + PA_H + off, &g_Xh[p][n0 + r][k0 + j * 8]);
            cp16(st + PA_L + off, &g_Xl[p][n0 + r][k0 + j * 8]);
            cp16(st + PB_H + off, &g_Wh[s][o0 + r][k0 + j * 8]);
            cp16(st + PB_L + off, &g_Wl[s][o0 + r][k0 + j * 8]);
        }
        CP_COMMIT();
    };
    issue(0);
    issue(1);

    float cS[2][8][4] = {};

    for (int kc = 0; kc < 4; kc++) {
        CP_WAIT(1);
        __syncthreads();
        const char* st = psm + (kc & 1) * PSTAGE;

        #pragma unroll
        for (int kt = 0; kt < 4; kt++) {
            int kb = kt * 32 + c4 * 4;
            uint32_t ah[2][4], al[2][4];
            #pragma unroll
            for (int mt = 0; mt < 2; mt++) {
                int r = wm * 32 + mt * 16 + r4;
                const char* a_h = st + PA_H + r * PJS + kb;
                const char* a_l = st + PA_L + r * PJS + kb;
                ah[mt][0] = *(const uint32_t*)a_h;
                ah[mt][1] = *(const uint32_t*)(a_h + 8 * PJS);
                ah[mt][2] = *(const uint32_t*)(a_h + 16);
                ah[mt][3] = *(const uint32_t*)(a_h + 8 * PJS + 16);
                al[mt][0] = *(const uint32_t*)a_l;
                al[mt][1] = *(const uint32_t*)(a_l + 8 * PJS);
                al[mt][2] = *(const uint32_t*)(a_l + 16);
                al[mt][3] = *(const uint32_t*)(a_l + 8 * PJS + 16);
            }
            #pragma unroll
            for (int nt = 0; nt < 8; nt++) {
                int o = wn * 64 + nt * 8 + r4;
                const char* b_h = st + PB_H + o * PJS + kb;
                const char* b_l = st + PB_L + o * PJS + kb;
                uint32_t bh0 = *(const uint32_t*)b_h;
                uint32_t bh1 = *(const uint32_t*)(b_h + 16);
                uint32_t bl0 = *(const uint32_t*)b_l;
                uint32_t bl1 = *(const uint32_t*)(b_l + 16);
                #pragma unroll
                for (int mt = 0; mt < 2; mt++) {
                    mma16(cS[mt][nt], ah[mt], bh0, bh1);
                    mma16(cS[mt][nt], al[mt], bh0, bh1);
                    mma16(cS[mt][nt], ah[mt], bl0, bl1);
                }
            }
        }
        __syncthreads();
        if (kc < 2) issue(kc + 2);
    }

    #pragma unroll
    for (int mt = 0; mt < 2; mt++) {
        int n_lo = n0 + wm * 32 + mt * 16 + r4;
        int n_hi = n_lo + 8;
        #pragma unroll
        for (int nt = 0; nt < 8; nt++) {
            int ol = wn * 64 + nt * 8 + 2 * c4;
            int og = o0 + ol;
            float b0 = bias[ol], b1 = bias[ol + 1];
            float y00 = cS[mt][nt][0] + b0, y01 = cS[mt][nt][1] + b1;
            float y10 = cS[mt][nt][2] + b0, y11 = cS[mt][nt][3] + b1;
            if (og < 64) {
                __nv_bfloat16 h00 = __float2bfloat16(y00), h01 = __float2bfloat16(y01);
                __nv_bfloat16 h10 = __float2bfloat16(y10), h11 = __float2bfloat16(y11);
                uint16_t u00 = *(uint16_t*)&h00, u01 = *(uint16_t*)&h01;
                uint16_t u10 = *(uint16_t*)&h10, u11 = *(uint16_t*)&h11;
                *(uint32_t*)&g_Qh[p][n_lo][og] = ((uint32_t)u01 << 16) | u00;
                *(uint32_t*)&g_Qh[p][n_hi][og] = ((uint32_t)u11 << 16) | u10;
                *(uint32_t*)&g_Ql[p][n_lo][og] =
                    pack_bf16(y00 - __bfloat162float(h00), y01 - __bfloat162float(h01));
                *(uint32_t*)&g_Ql[p][n_hi][og] =
                    pack_bf16(y10 - __bfloat162float(h10), y11 - __bfloat162float(h11));
            } else if (og < 128) {
                int oo = og - 64;
                __nv_bfloat16 h00 = __float2bfloat16(y00), h01 = __float2bfloat16(y01);
                __nv_bfloat16 h10 = __float2bfloat16(y10), h11 = __float2bfloat16(y11);
                uint16_t u00 = *(uint16_t*)&h00, u01 = *(uint16_t*)&h01;
                uint16_t u10 = *(uint16_t*)&h10, u11 = *(uint16_t*)&h11;
                *(uint32_t*)&g_Kh[p][n_lo][oo] = ((uint32_t)u01 << 16) | u00;
                *(uint32_t*)&g_Kh[p][n_hi][oo] = ((uint32_t)u11 << 16) | u10;
                *(uint32_t*)&g_Kl[p][n_lo][oo] =
                    pack_bf16(y00 - __bfloat162float(h00), y01 - __bfloat162float(h01));
                *(uint32_t*)&g_Kl[p][n_hi][oo] =
                    pack_bf16(y10 - __bfloat162float(h10), y11 - __bfloat162float(h11));
            } else {
                int c = og - 128;
                g_V[p][c][n_lo]     = __float2half(y00);
                g_V[p][c + 1][n_lo] = __float2half(y01);
                g_V[p][c][n_hi]     = __float2half(y10);
                g_V[p][c + 1][n_hi] = __float2half(y11);
            }
        }
    }
}

// ---------------------------------------------------------------------------
// Flash attention: 128-row tiles, 8 warps (4M x 2N), 1 CTA/SM.
// Double-buffered K and V (3 barriers/tile). PV split: local half from
// registers (pre-barrier), cross half from smem (post-barrier).
// ---------------------------------------------------------------------------
#define QKSB 144
#define KBUFB 18432u                                 // one K buf: KH(9216)+KL(9216)
#define OFF_K  0u                                    // 2 bufs = 36864
#define VBUFB 36864u                                 // one V buf: 256ch x 144B
#define OFF_V0 36864u                                // 2 bufs = 73728 (ends 110592)
#define OFF_QH 110592u
#define OFF_QL 129024u
#define OFF_P  147456u                               // 128 rows x 144B fp16
#define OFF_L  165888u
#define OFF_PM 166400u
#define SMEM_TOTAL 167424u

__global__ __launch_bounds__(256, 1)
void flash_attn(const float* __restrict__ in1, const float* __restrict__ in2,
                const float* __restrict__ gamma, float* __restrict__ out)
{
    extern __shared__ __align__(16) char smem[];
    float* lrow = (float*)(smem + OFF_L);
    float* pmax = (float*)(smem + OFF_PM);
    uint32_t sb = smem_u32(smem);

    int tid  = threadIdx.x;
    int p    = blockIdx.y;
    int i0   = blockIdx.x * 128;
    int warp = tid >> 5, lane = tid & 31;
    int wm = warp >> 1, wn = warp & 1;       // 4M x 2N
    int r4 = lane >> 2, c4 = lane & 3;
    int lm = lane >> 3, lr = lane & 7;
    int mrow = wm * 32;

    uint32_t aRow = (uint32_t)((lm & 1) * 8 + lr) * QKSB + (uint32_t)((lm >> 1) * 16);
    uint32_t bRow = (uint32_t)((lm >> 1) * 8 + lr) * QKSB + (uint32_t)((lm & 1) * 16);

    if (tid < 128) lrow[tid] = 0.f;

    // ---- prefetch: group1 = Q(h,l) + K(0); group2 = V(0) ----
    {
        #pragma unroll
        for (int i = 0; i < 8; i++) {
            int m = tid + i * 256;
            int r = (m & 1023) >> 3, j = m & 7;
            if (m < 1024)
                cp16(sb + OFF_QH + (uint32_t)(r * QKSB + j * 16), &g_Qh[p][i0 + r][j * 8]);
            else
                cp16(sb + OFF_QL + (uint32_t)(r * QKSB + j * 16), &g_Ql[p][i0 + r][j * 8]);
        }
        #pragma unroll
        for (int i = 0; i < 4; i++) {
            int m = tid + i * 256;
            int r = (m & 511) >> 3, j = m & 7;
            if (m < 512)
                cp16(sb + OFF_K + (uint32_t)(r * QKSB + j * 16), &g_Kh[p][r][j * 8]);
            else
                cp16(sb + OFF_K + 9216u + (uint32_t)(r * QKSB + j * 16), &g_Kl[p][r][j * 8]);
        }
        CP_COMMIT();
        #pragma unroll
        for (int i = 0; i < 8; i++) {
            int m = tid + i * 256;
            int ch = m >> 3, j = m & 7;
            cp16(sb + OFF_V0 + (uint32_t)(ch * QKSB + j * 16), &g_V[p][ch][j * 8]);
        }
        CP_COMMIT();
    }

    float O[2][16][4];
    #pragma unroll
    for (int mt = 0; mt < 2; mt++)
        #pragma unroll
        for (int nt = 0; nt < 16; nt++)
            #pragma unroll
            for (int i = 0; i < 4; i++) O[mt][nt][i] = 0.f;

    float lsum[2][2] = {};
    float m_run[2][2] = {{-1e30f, -1e30f}, {-1e30f, -1e30f}};

    for (int jt = 0; jt < 64; jt++) {
        CP_WAIT(0);
        __syncthreads();   // sync_A: K(jt), V(jt) visible; prior-tile readers done

        uint32_t kbase = sb + OFF_K  + (uint32_t)(jt & 1) * KBUFB;
        uint32_t vbase = sb + OFF_V0 + (uint32_t)(jt & 1) * VBUFB;

        // ---- prefetch V(jt+1) into alt buffer (its readers passed sync_A) ----
        if (jt < 63) {
            int j0n = (jt + 1) << 6;
            uint32_t vdst = sb + OFF_V0 + (uint32_t)((jt + 1) & 1) * VBUFB;
            #pragma unroll
            for (int i = 0; i < 8; i++) {
                int m = tid + i * 256;
                int ch = m >> 3, j = m & 7;
                cp16(vdst + (uint32_t)(ch * QKSB + j * 16), &g_V[p][ch][j0n + j * 8]);
            }
            CP_COMMIT();
        }

        // ---- S = QK^T: 3-term split-bf16 (ldmatrix) ----
        float cS[2][4][4];
        #pragma unroll
        for (int mt = 0; mt < 2; mt++)
            #pragma unroll
            for (int nt = 0; nt < 4; nt++)
                #pragma unroll
                for (int i = 0; i < 4; i++) cS[mt][nt][i] = 0.f;

        #pragma unroll
        for (int kt = 0; kt < 4; kt++) {
            uint32_t kbyte = (uint32_t)kt * 32u;
            uint32_t ah[2][4], al[2][4];
            #pragma unroll
            for (int mt = 0; mt < 2; mt++) {
                uint32_t qaddr = sb + OFF_QH + (uint32_t)(mrow + mt * 16) * QKSB + kbyte + aRow;
                ldsm4(ah[mt], qaddr);
                ldsm4(al[mt], qaddr + (OFF_QL - OFF_QH));
            }
            #pragma unroll
            for (int ntp = 0; ntp < 2; ntp++) {
                uint32_t kaddr = kbase + (uint32_t)(wn * 32 + ntp * 16) * QKSB + kbyte + bRow;
                uint32_t bh[4], bl[4];
                ldsm4(bh, kaddr);
                ldsm4(bl, kaddr + 9216u);
                #pragma unroll
                for (int mt = 0; mt < 2; mt++) {
                    mma16(cS[mt][2 * ntp],     ah[mt], bh[0], bh[1]);
                    mma16(cS[mt][2 * ntp],     al[mt], bh[0], bh[1]);
                    mma16(cS[mt][2 * ntp],     ah[mt], bl[0], bl[1]);
                    mma16(cS[mt][2 * ntp + 1], ah[mt], bh[2], bh[3]);
                    mma16(cS[mt][2 * ntp + 1], al[mt], bh[2], bh[3]);
                    mma16(cS[mt][2 * ntp + 1], ah[mt], bl[2], bl[3]);
                }
            }
        }

        // ---- warp-local partial row max ----
        float pm[2][2];
        #pragma unroll
        for (int mt = 0; mt < 2; mt++) {
            float m0 = -1e30f, m1 = -1e30f;
            #pragma unroll
            for (int nt = 0; nt < 4; nt++) {
                m0 = fmaxf(m0, fmaxf(cS[mt][nt][0], cS[mt][nt][1]));
                m1 = fmaxf(m1, fmaxf(cS[mt][nt][2], cS[mt][nt][3]));
            }
            m0 = fmaxf(m0, __shfl_xor_sync(0xffffffffu, m0, 1));
            m0 = fmaxf(m0, __shfl_xor_sync(0xffffffffu, m0, 2));
            m1 = fmaxf(m1, __shfl_xor_sync(0xffffffffu, m1, 1));
            m1 = fmaxf(m1, __shfl_xor_sync(0xffffffffu, m1, 2));
            pm[mt][0] = m0; pm[mt][1] = m1;
        }
        if (c4 == 0) {
            #pragma unroll
            for (int mt = 0; mt < 2; mt++) {
                int r = mrow + mt * 16 + r4;
                pmax[wn * 128 + r]     = pm[mt][0];
                pmax[wn * 128 + r + 8] = pm[mt][1];
            }
        }
        __syncthreads();   // sync_B: pmax visible; K(jt) consumed by all

        // ---- prefetch K(jt+1) into alt buffer ----
        if (jt < 63) {
            int j0n = (jt + 1) << 6;
            uint32_t kdst = sb + OFF_K + (uint32_t)((jt + 1) & 1) * KBUFB;
            #pragma unroll
            for (int i = 0; i < 4; i++) {
                int m = tid + i * 256;
                int r = (m & 511) >> 3, j = m & 7;
                if (m < 512)
                    cp16(kdst + (uint32_t)(r * QKSB + j * 16), &g_Kh[p][j0n + r][j * 8]);
                else
                    cp16(kdst + 9216u + (uint32_t)(r * QKSB + j * 16), &g_Kl[p][j0n + r][j * 8]);
            }
            CP_COMMIT();
        }

        // ---- combined max, alpha, O-rescale ----
        float m_new[2][2], alpha[2][2];
        #pragma unroll
        for (int mt = 0; mt < 2; mt++) {
            #pragma unroll
            for (int h = 0; h < 2; h++) {
                int r = mrow + mt * 16 + r4 + 8 * h;
                float mt_tile = fmaxf(pmax[r], pmax[128 + r]);
                m_new[mt][h] = fmaxf(m_run[mt][h], mt_tile);
                alpha[mt][h] = __expf(m_run[mt][h] - m_new[mt][h]);
                m_run[mt][h] = m_new[mt][h];
            }
        }
        bool anyr = (alpha[0][0] < 1.f) | (alpha[0][1] < 1.f)
                  | (alpha[1][0] < 1.f) | (alpha[1][1] < 1.f);
        if (__any_sync(0xffffffffu, anyr)) {
            #pragma unroll
            for (int mt = 0; mt < 2; mt++)
                #pragma unroll
                for (int nt = 0; nt < 16; nt++) {
                    O[mt][nt][0] *= alpha[mt][0];
                    O[mt][nt][1] *= alpha[mt][0];
                    O[mt][nt][2] *= alpha[mt][1];
                    O[mt][nt][3] *= alpha[mt][1];
                }
        }

        // ---- exp, pack fp16 P (kept in regs AND stored to smem) ----
        uint32_t pk[2][4][2];
        #pragma unroll
        for (int mt = 0; mt < 2; mt++) {
            int r = mrow + mt * 16 + r4;
            float s0 = 0.f, s1 = 0.f;
            #pragma unroll
            for (int nt = 0; nt < 4; nt++) {
                int col = wn * 32 + nt * 8 + 2 * c4;
                float e0 = __expf(cS[mt][nt][0] - m_new[mt][0]);
                float e1 = __expf(cS[mt][nt][1] - m_new[mt][0]);
                float e2 = __expf(cS[mt][nt][2] - m_new[mt][1]);
                float e3 = __expf(cS[mt][nt][3] - m_new[mt][1]);
                s0 += e0 + e1;
                s1 += e2 + e3;
                pk[mt][nt][0] = pack_f16(e0, e1);
                pk[mt][nt][1] = pack_f16(e2, e3);
                *(uint32_t*)(smem + OFF_P + r * QKSB + col * 2)       = pk[mt][nt][0];
                *(uint32_t*)(smem + OFF_P + (r + 8) * QKSB + col * 2) = pk[mt][nt][1];
            }
            lsum[mt][0] = lsum[mt][0] * alpha[mt][0] + s0;
            lsum[mt][1] = lsum[mt][1] * alpha[mt][1] + s1;
        }

        // ---- LOCAL-half PV from registers (no barrier needed; V visible since sync_A) ----
        #pragma unroll
        for (int lc = 0; lc < 2; lc++) {
            uint32_t kbyte = (uint32_t)((wn * 2 + lc) * 32);
            uint32_t pa0[4] = { pk[0][2 * lc][0], pk[0][2 * lc][1],
                                pk[0][2 * lc + 1][0], pk[0][2 * lc + 1][1] };
            uint32_t pa1[4] = { pk[1][2 * lc][0], pk[1][2 * lc][1],
                                pk[1][2 * lc + 1][0], pk[1][2 * lc + 1][1] };
            #pragma unroll
            for (int ntp = 0; ntp < 8; ntp++) {
                uint32_t vaddr = vbase + (uint32_t)(wn * 128 + ntp * 16) * QKSB + kbyte + bRow;
                uint32_t vb[4];
                ldsm4(vb, vaddr);
                mma16f(O[0][2 * ntp],     pa0, vb[0], vb[1]);
                mma16f(O[1][2 * ntp],     pa1, vb[0], vb[1]);
                mma16f(O[0][2 * ntp + 1], pa0, vb[2], vb[3]);
                mma16f(O[1][2 * ntp + 1], pa1, vb[2], vb[3]);
            }
        }
        __syncthreads();   // sync_C: partner's P visible

        // ---- CROSS-half PV from smem P (partner's 32 cols) ----
        #pragma unroll
        for (int lc = 0; lc < 2; lc++) {
            uint32_t kbyte = (uint32_t)(((1 - wn) * 2 + lc) * 32);
            uint32_t pa[2][4];
            #pragma unroll
            for (int mt = 0; mt < 2; mt++) {
                uint32_t paddr = sb + OFF_P + (uint32_t)(mrow + mt * 16) * QKSB + kbyte + aRow;
                ldsm4(pa[mt], paddr);
            }
            #pragma unroll
            for (int ntp = 0; ntp < 8; ntp++) {
                uint32_t vaddr = vbase + (uint32_t)(wn * 128 + ntp * 16) * QKSB + kbyte + bRow;
                uint32_t vb[4];
                ldsm4(vb, vaddr);
                mma16f(O[0][2 * ntp],     pa[0], vb[0], vb[1]);
                mma16f(O[1][2 * ntp],     pa[1], vb[0], vb[1]);
                mma16f(O[0][2 * ntp + 1], pa[0], vb[2], vb[3]);
                mma16f(O[1][2 * ntp + 1], pa[1], vb[2], vb[3]);
            }
        }
    }

    // ---- row-sum reduction ----
    #pragma unroll
    for (int mt = 0; mt < 2; mt++)
        #pragma unroll
        for (int h = 0; h < 2; h++) {
            float v = lsum[mt][h];
            v += __shfl_xor_sync(0xffffffffu, v, 1);
            v += __shfl_xor_sync(0xffffffffu, v, 2);
            if (c4 == 0) atomicAdd(&lrow[mrow + mt * 16 + r4 + 8 * h], v);
        }
    __syncthreads();

    // ---- epilogue ----
    float gm = gamma[0];
    int s = p >> 1, b = p & 1;
    const float* xin = (s ? in2 : in1) + (size_t)b * CC * NPIX;
    float* o = out + (size_t)p * CC * NPIX;
    #pragma unroll
    for (int mt = 0; mt < 2; mt++) {
        int rlo = mrow + mt * 16 + r4, rhi = rlo + 8;
        float sclo = gm / lrow[rlo];
        float schi = gm / lrow[rhi];
        size_t nlo = (size_t)(i0 + rlo), nhi = (size_t)(i0 + rhi);
        #pragma unroll
        for (int nt = 0; nt < 16; nt++) {
            int ch = wn * 128 + nt * 8 + 2 * c4;
            o[(size_t)ch * NPIX + nlo]       = O[mt][nt][0] * sclo + xin[(size_t)ch * NPIX + nlo];
            o[(size_t)(ch + 1) * NPIX + nlo] = O[mt][nt][1] * sclo + xin[(size_t)(ch + 1) * NPIX + nlo];
            o[(size_t)ch * NPIX + nhi]       = O[mt][nt][2] * schi + xin[(size_t)ch * NPIX + nhi];
            o[(size_t)(ch + 1) * NPIX + nhi] = O[mt][nt][3] * schi + xin[(size_t)(ch + 1) * NPIX + nhi];
        }
    }
}

// ---------------------------------------------------------------------------
extern "C" void kernel_launch(void* const* d_in, const int* in_sizes, int n_in,
                              void* d_out, int out_size)
{
    const float* in1 = (const float*)d_in[0];
    const float* in2 = (const float*)d_in[1];
    const float* q1w = (const float*)d_in[2];  const float* q1b = (const float*)d_in[3];
    const float* k1w = (const float*)d_in[4];  const float* k1b = (const float*)d_in[5];
    const float* v1w = (const float*)d_in[6];  const float* v1b = (const float*)d_in[7];
    const float* q2w = (const float*)d_in[8];  const float* q2b = (const float*)d_in[9];
    const float* k2w = (const float*)d_in[10]; const float* k2b = (const float*)d_in[11];
    const float* v2w = (const float*)d_in[12]; const float* v2b = (const float*)d_in[13];
    const float* gamma = (const float*)d_in[22];
    float* out = (float*)d_out;

    prep_weights<<<dim3(384, 2), 256>>>(q1w, q1b, k1w, k1b, v1w, v1b,
                                        q2w, q2b, k2w, k2b, v2w, v2b);
    convert_x<<<dim3(64, 4, 4), 256>>>(in1, in2);

    cudaFuncSetAttribute(proj_mma, cudaFuncAttributeMaxDynamicSharedMemorySize, (int)PSMEM);
    proj_mma<<<dim3(32, 3, 4), 256, PSMEM>>>();

    cudaFuncSetAttribute(flash_attn, cudaFuncAttributeMaxDynamicSharedMemorySize, (int)SMEM_TOTAL);
    flash_attn<<<dim3(32, 4), 256, SMEM_TOTAL>>>(in1, in2, gamma, out);
}

// round 13
// speedup vs baseline: 1.2884x; 1.0389x over previous
#include <cuda_runtime.h>
#include <cuda_bf16.h>
#include <cuda_fp16.h>
#include <cstdint>

#define CC    256
#define CQ    64
#define NPIX  4096
#define NPAIR 4

// ---------------- helpers ----------------
__device__ __forceinline__ uint32_t smem_u32(const void* p) {
    uint32_t a;
    asm("{ .reg .u64 t; cvta.to.shared.u64 t, %1; cvt.u32.u64 %0, t; }" : "=r"(a) : "l"(p));
    return a;
}

__device__ __forceinline__ void cp16(uint32_t s, const void* g) {
    asm volatile("cp.async.cg.shared.global [%0], [%1], 16;" :: "r"(s), "l"(g) : "memory");
}
#define CP_COMMIT()  asm volatile("cp.async.commit_group;" ::: "memory")
#define CP_WAIT(N)   asm volatile("cp.async.wait_group %0;" :: "n"(N) : "memory")

// ldmatrix x4: four 8x8 b16 matrices -> 4 regs
__device__ __forceinline__ void ldsm4(uint32_t r[4], uint32_t addr) {
    asm volatile("ldmatrix.sync.aligned.m8n8.x4.shared.b16 {%0,%1,%2,%3}, [%4];"
        : "=r"(r[0]), "=r"(r[1]), "=r"(r[2]), "=r"(r[3]) : "r"(addr));
}

// m16n8k16 bf16 mma (S phase + proj)
__device__ __forceinline__ void mma16(float c[4], const uint32_t a[4], uint32_t b0, uint32_t b1) {
    asm volatile(
        "mma.sync.aligned.m16n8k16.row.col.f32.bf16.bf16.f32 "
        "{%0,%1,%2,%3}, {%4,%5,%6,%7}, {%8,%9}, {%0,%1,%2,%3};"
        : "+f"(c[0]), "+f"(c[1]), "+f"(c[2]), "+f"(c[3])
        : "r"(a[0]), "r"(a[1]), "r"(a[2]), "r"(a[3]), "r"(b0), "r"(b1));
}

// m16n8k16 fp16 mma (PV phase)
__device__ __forceinline__ void mma16f(float c[4], const uint32_t a[4], uint32_t b0, uint32_t b1) {
    asm volatile(
        "mma.sync.aligned.m16n8k16.row.col.f32.f16.f16.f32 "
        "{%0,%1,%2,%3}, {%4,%5,%6,%7}, {%8,%9}, {%0,%1,%2,%3};"
        : "+f"(c[0]), "+f"(c[1]), "+f"(c[2]), "+f"(c[3])
        : "r"(a[0]), "r"(a[1]), "r"(a[2]), "r"(a[3]), "r"(b0), "r"(b1));
}

__device__ __forceinline__ uint32_t pack_bf16(float a, float b) {
    __nv_bfloat16 h0 = __float2bfloat16(a), h1 = __float2bfloat16(b);
    uint16_t u0 = *(uint16_t*)&h0, u1 = *(uint16_t*)&h1;
    return ((uint32_t)u1 << 16) | u0;
}

__device__ __forceinline__ uint32_t pack_f16(float a, float b) {
    __half2 h = __floats2half2_rn(a, b);
    return *(uint32_t*)&h;
}

// ---------------- scratch ----------------
__device__ float g_Bias[2][384];
__device__ __nv_bfloat16 g_Wh[2][384][CC];
__device__ __nv_bfloat16 g_Wl[2][384][CC];
__device__ __nv_bfloat16 g_Xh[NPAIR][NPIX][CC];
__device__ __nv_bfloat16 g_Xl[NPAIR][NPIX][CC];
__device__ __nv_bfloat16 g_Qh[NPAIR][NPIX][CQ];
__device__ __nv_bfloat16 g_Ql[NPAIR][NPIX][CQ];
__device__ __nv_bfloat16 g_Kh[NPAIR][NPIX][CQ];
__device__ __nv_bfloat16 g_Kl[NPAIR][NPIX][CQ];
__device__ __half g_V[NPAIR][CC][NPIX];          // channel-major fp16 V

// ---------------------------------------------------------------------------
__global__ void prep_weights(
    const float* __restrict__ q1w, const float* __restrict__ q1b,
    const float* __restrict__ k1w, const float* __restrict__ k1b,
    const float* __restrict__ v1w, const float* __restrict__ v1b,
    const float* __restrict__ q2w, const float* __restrict__ q2b,
    const float* __restrict__ k2w, const float* __restrict__ k2b,
    const float* __restrict__ v2w, const float* __restrict__ v2b)
{
    int o = blockIdx.x, s = blockIdx.y;
    const float* w; const float* bsrc; int row;
    if (o < 64)       { w = s ? q2w : q1w; bsrc = s ? q2b : q1b; row = o; }
    else if (o < 128) { w = s ? k2w : k1w; bsrc = s ? k2b : k1b; row = o - 64; }
    else              { w = s ? v2w : v1w; bsrc = s ? v2b : v1b; row = o - 128; }
    float v = w[row * CC + threadIdx.x];
    __nv_bfloat16 h = __float2bfloat16(v);
    g_Wh[s][o][threadIdx.x] = h;
    g_Wl[s][o][threadIdx.x] = __float2bfloat16(v - __bfloat162float(h));
    if (threadIdx.x == 0) g_Bias[s][o] = bsrc[row];
}

// ---------------------------------------------------------------------------
__global__ __launch_bounds__(256) void convert_x(
    const float* __restrict__ in1, const float* __restrict__ in2)
{
    __shared__ float t[64][65];
    int p = blockIdx.z, s = p >> 1, b = p & 1;
    const float* x = (s ? in2 : in1) + (size_t)b * CC * NPIX;
    int n0 = blockIdx.x * 64, c0 = blockIdx.y * 64;
    int tid = threadIdx.x;

    #pragma unroll
    for (int i = 0; i < 4; i++) {
        int m = tid + i * 256;
        int c = m >> 4, nn = (m & 15) << 2;
        float4 v = *(const float4*)&x[(size_t)(c0 + c) * NPIX + n0 + nn];
        t[c][nn] = v.x; t[c][nn + 1] = v.y; t[c][nn + 2] = v.z; t[c][nn + 3] = v.w;
    }
    __syncthreads();

    int n = tid >> 2, cb = (tid & 3) << 4;
    uint32_t hw[8], lw[8];
    #pragma unroll
    for (int j = 0; j < 8; j++) {
        float v0 = t[cb + 2 * j][n], v1 = t[cb + 2 * j + 1][n];
        __nv_bfloat16 h0 = __float2bfloat16(v0);
        __nv_bfloat16 h1 = __float2bfloat16(v1);
        float l0 = v0 - __bfloat162float(h0);
        float l1 = v1 - __bfloat162float(h1);
        uint16_t a0 = *(uint16_t*)&h0, a1 = *(uint16_t*)&h1;
        hw[j] = ((uint32_t)a1 << 16) | a0;
        lw[j] = pack_bf16(l0, l1);
    }
    uint4* dh = (uint4*)&g_Xh[p][n0 + n][c0 + cb];
    uint4* dl = (uint4*)&g_Xl[p][n0 + n][c0 + cb];
    dh[0] = make_uint4(hw[0], hw[1], hw[2], hw[3]);
    dh[1] = make_uint4(hw[4], hw[5], hw[6], hw[7]);
    dl[0] = make_uint4(lw[0], lw[1], lw[2], lw[3]);
    dl[1] = make_uint4(lw[4], lw[5], lw[6], lw[7]);
}

// ---------------------------------------------------------------------------
// Tensorized projection (unchanged)
// ---------------------------------------------------------------------------
#define PJS 144u
#define PA_H 0u
#define PA_L 18432u
#define PB_H 36864u
#define PB_L 55296u
#define PSTAGE 73728u
#define POFF_BIAS 147456u
#define PSMEM 147968u

__global__ __launch_bounds__(256, 1) void proj_mma()
{
    extern __shared__ __align__(16) char psm[];
    uint32_t sb = smem_u32(psm);
    float* bias = (float*)(psm + POFF_BIAS);
    int tid = threadIdx.x;
    int p = blockIdx.z, s = p >> 1;
    int n0 = blockIdx.x * 128, o0 = blockIdx.y * 128;
    int warp = tid >> 5, lane = tid & 31;
    int wm = warp >> 1, wn = warp & 1;
    int r4 = lane >> 2, c4 = lane & 3;

    if (tid < 128) bias[tid] = g_Bias[s][o0 + tid];

    auto issue = [&](int kc) {
        uint32_t st = sb + (uint32_t)(kc & 1) * PSTAGE;
        int k0 = kc * 64;
        #pragma unroll
        for (int i = 0; i < 4; i++) {
            int m = tid + i * 256;
            int r = m >> 3, j = m & 7;
            uint32_t off = (uint32_t)r * PJS + (uint32_t)j * 16u;
            cp16(st + PA_H + off, &g_Xh[p][n0 + r][k0 + j * 8]);
            cp16(st + PA_L + off, &g_Xl[p][n0 + r][k0 + j * 8]);
            cp16(st + PB_H + off, &g_Wh[s][o0 + r][k0 + j * 8]);
            cp16(st + PB_L + off, &g_Wl[s][o0 + r][k0 + j * 8]);
        }
        CP_COMMIT();
    };
    issue(0);
    issue(1);

    float cS[2][8][4] = {};

    for (int kc = 0; kc < 4; kc++) {
        CP_WAIT(1);
        __syncthreads();
        const char* st = psm + (kc & 1) * PSTAGE;

        #pragma unroll
        for (int kt = 0; kt < 4; kt++) {
            int kb = kt * 32 + c4 * 4;
            uint32_t ah[2][4], al[2][4];
            #pragma unroll
            for (int mt = 0; mt < 2; mt++) {
                int r = wm * 32 + mt * 16 + r4;
                const char* a_h = st + PA_H + r * PJS + kb;
                const char* a_l = st + PA_L + r * PJS + kb;
                ah[mt][0] = *(const uint32_t*)a_h;
                ah[mt][1] = *(const uint32_t*)(a_h + 8 * PJS);
                ah[mt][2] = *(const uint32_t*)(a_h + 16);
                ah[mt][3] = *(const uint32_t*)(a_h + 8 * PJS + 16);
                al[mt][0] = *(const uint32_t*)a_l;
                al[mt][1] = *(const uint32_t*)(a_l + 8 * PJS);
                al[mt][2] = *(const uint32_t*)(a_l + 16);
                al[mt][3] = *(const uint32_t*)(a_l + 8 * PJS + 16);
            }
            #pragma unroll
            for (int nt = 0; nt < 8; nt++) {
                int o = wn * 64 + nt * 8 + r4;
                const char* b_h = st + PB_H + o * PJS + kb;
                const char* b_l = st + PB_L + o * PJS + kb;
                uint32_t bh0 = *(const uint32_t*)b_h;
                uint32_t bh1 = *(const uint32_t*)(b_h + 16);
                uint32_t bl0 = *(const uint32_t*)b_l;
                uint32_t bl1 = *(const uint32_t*)(b_l + 16);
                #pragma unroll
                for (int mt = 0; mt < 2; mt++) {
                    mma16(cS[mt][nt], ah[mt], bh0, bh1);
                    mma16(cS[mt][nt], al[mt], bh0, bh1);
                    mma16(cS[mt][nt], ah[mt], bl0, bl1);
                }
            }
        }
        __syncthreads();
        if (kc < 2) issue(kc + 2);
    }

    #pragma unroll
    for (int mt = 0; mt < 2; mt++) {
        int n_lo = n0 + wm * 32 + mt * 16 + r4;
        int n_hi = n_lo + 8;
        #pragma unroll
        for (int nt = 0; nt < 8; nt++) {
            int ol = wn * 64 + nt * 8 + 2 * c4;
            int og = o0 + ol;
            float b0 = bias[ol], b1 = bias[ol + 1];
            float y00 = cS[mt][nt][0] + b0, y01 = cS[mt][nt][1] + b1;
            float y10 = cS[mt][nt][2] + b0, y11 = cS[mt][nt][3] + b1;
            if (og < 64) {
                __nv_bfloat16 h00 = __float2bfloat16(y00), h01 = __float2bfloat16(y01);
                __nv_bfloat16 h10 = __float2bfloat16(y10), h11 = __float2bfloat16(y11);
                uint16_t u00 = *(uint16_t*)&h00, u01 = *(uint16_t*)&h01;
                uint16_t u10 = *(uint16_t*)&h10, u11 = *(uint16_t*)&h11;
                *(uint32_t*)&g_Qh[p][n_lo][og] = ((uint32_t)u01 << 16) | u00;
                *(uint32_t*)&g_Qh[p][n_hi][og] = ((uint32_t)u11 << 16) | u10;
                *(uint32_t*)&g_Ql[p][n_lo][og] =
                    pack_bf16(y00 - __bfloat162float(h00), y01 - __bfloat162float(h01));
                *(uint32_t*)&g_Ql[p][n_hi][og] =
                    pack_bf16(y10 - __bfloat162float(h10), y11 - __bfloat162float(h11));
            } else if (og < 128) {
                int oo = og - 64;
                __nv_bfloat16 h00 = __float2bfloat16(y00), h01 = __float2bfloat16(y01);
                __nv_bfloat16 h10 = __float2bfloat16(y10), h11 = __float2bfloat16(y11);
                uint16_t u00 = *(uint16_t*)&h00, u01 = *(uint16_t*)&h01;
                uint16_t u10 = *(uint16_t*)&h10, u11 = *(uint16_t*)&h11;
                *(uint32_t*)&g_Kh[p][n_lo][oo] = ((uint32_t)u01 << 16) | u00;
                *(uint32_t*)&g_Kh[p][n_hi][oo] = ((uint32_t)u11 << 16) | u10;
                *(uint32_t*)&g_Kl[p][n_lo][oo] =
                    pack_bf16(y00 - __bfloat162float(h00), y01 - __bfloat162float(h01));
                *(uint32_t*)&g_Kl[p][n_hi][oo] =
                    pack_bf16(y10 - __bfloat162float(h10), y11 - __bfloat162float(h11));
            } else {
                int c = og - 128;
                g_V[p][c][n_lo]     = __float2half(y00);
                g_V[p][c + 1][n_lo] = __float2half(y01);
                g_V[p][c][n_hi]     = __float2half(y10);
                g_V[p][c + 1][n_hi] = __float2half(y11);
            }
        }
    }
}

// ---------------------------------------------------------------------------
// Flash attention: 128-row tiles, 8 warps (4M x 2N), 1 CTA/SM.
// TWO barriers/tile: K double-buffered, V TRIPLE-buffered so all cross-warp
// hazards are separated by >=1 barrier even with a full phase of warp skew.
// PV split: local half from registers, cross half from smem P.
// ---------------------------------------------------------------------------
#define QKSB 144
#define KBUFB 18432u
#define OFF_K   0u                                   // 2 K bufs  -> 36864
#define VBUFB  36864u
#define OFF_V0  36864u                               // 3 V bufs  -> 110592 (ends 147456)
#define OFF_QH 147456u
#define OFF_QL 165888u
#define OFF_P  184320u                               // 128 rows x 144B fp16
#define OFF_L  202752u
#define OFF_PM 203264u
#define SMEM_TOTAL 204288u

__global__ __launch_bounds__(256, 1)
void flash_attn(const float* __restrict__ in1, const float* __restrict__ in2,
                const float* __restrict__ gamma, float* __restrict__ out)
{
    extern __shared__ __align__(16) char smem[];
    float* lrow = (float*)(smem + OFF_L);
    float* pmax = (float*)(smem + OFF_PM);
    uint32_t sb = smem_u32(smem);

    int tid  = threadIdx.x;
    int p    = blockIdx.y;
    int i0   = blockIdx.x * 128;
    int warp = tid >> 5, lane = tid & 31;
    int wm = warp >> 1, wn = warp & 1;       // 4M x 2N
    int r4 = lane >> 2, c4 = lane & 3;
    int lm = lane >> 3, lr = lane & 7;
    int mrow = wm * 32;

    uint32_t aRow = (uint32_t)((lm & 1) * 8 + lr) * QKSB + (uint32_t)((lm >> 1) * 16);
    uint32_t bRow = (uint32_t)((lm >> 1) * 8 + lr) * QKSB + (uint32_t)((lm & 1) * 16);

    if (tid < 128) lrow[tid] = 0.f;

    // ---- prologue: load Q, K(0), V(0); wait; publish ----
    {
        #pragma unroll
        for (int i = 0; i < 8; i++) {
            int m = tid + i * 256;
            int r = (m & 1023) >> 3, j = m & 7;
            if (m < 1024)
                cp16(sb + OFF_QH + (uint32_t)(r * QKSB + j * 16), &g_Qh[p][i0 + r][j * 8]);
            else
                cp16(sb + OFF_QL + (uint32_t)(r * QKSB + j * 16), &g_Ql[p][i0 + r][j * 8]);
        }
        #pragma unroll
        for (int i = 0; i < 4; i++) {
            int m = tid + i * 256;
            int r = (m & 511) >> 3, j = m & 7;
            if (m < 512)
                cp16(sb + OFF_K + (uint32_t)(r * QKSB + j * 16), &g_Kh[p][r][j * 8]);
            else
                cp16(sb + OFF_K + 9216u + (uint32_t)(r * QKSB + j * 16), &g_Kl[p][r][j * 8]);
        }
        #pragma unroll
        for (int i = 0; i < 8; i++) {
            int m = tid + i * 256;
            int ch = m >> 3, j = m & 7;
            cp16(sb + OFF_V0 + (uint32_t)(ch * QKSB + j * 16), &g_V[p][ch][j * 8]);
        }
        CP_COMMIT();
        CP_WAIT(0);
        __syncthreads();
    }

    float O[2][16][4];
    #pragma unroll
    for (int mt = 0; mt < 2; mt++)
        #pragma unroll
        for (int nt = 0; nt < 16; nt++)
            #pragma unroll
            for (int i = 0; i < 4; i++) O[mt][nt][i] = 0.f;

    float lsum[2][2] = {};
    float m_run[2][2] = {{-1e30f, -1e30f}, {-1e30f, -1e30f}};

    int vc = 0;   // V buffer holding V(jt)

    for (int jt = 0; jt < 64; jt++) {
        uint32_t kbase = sb + OFF_K  + (uint32_t)(jt & 1) * KBUFB;
        uint32_t vbase = sb + OFF_V0 + (uint32_t)vc * VBUFB;
        int vn = vc + 1; if (vn == 3) vn = 0;

        // ---- prefetch V(jt+1) into third buffer (no hazard under mod-3) ----
        if (jt < 63) {
            int j0n = (jt + 1) << 6;
            uint32_t vdst = sb + OFF_V0 + (uint32_t)vn * VBUFB;
            #pragma unroll
            for (int i = 0; i < 8; i++) {
                int m = tid + i * 256;
                int ch = m >> 3, j = m & 7;
                cp16(vdst + (uint32_t)(ch * QKSB + j * 16), &g_V[p][ch][j0n + j * 8]);
            }
            CP_COMMIT();
        }

        // ---- S = QK^T: 3-term split-bf16 (ldmatrix) ----
        float cS[2][4][4];
        #pragma unroll
        for (int mt = 0; mt < 2; mt++)
            #pragma unroll
            for (int nt = 0; nt < 4; nt++)
                #pragma unroll
                for (int i = 0; i < 4; i++) cS[mt][nt][i] = 0.f;

        #pragma unroll
        for (int kt = 0; kt < 4; kt++) {
            uint32_t kbyte = (uint32_t)kt * 32u;
            uint32_t ah[2][4], al[2][4];
            #pragma unroll
            for (int mt = 0; mt < 2; mt++) {
                uint32_t qaddr = sb + OFF_QH + (uint32_t)(mrow + mt * 16) * QKSB + kbyte + aRow;
                ldsm4(ah[mt], qaddr);
                ldsm4(al[mt], qaddr + (OFF_QL - OFF_QH));
            }
            #pragma unroll
            for (int ntp = 0; ntp < 2; ntp++) {
                uint32_t kaddr = kbase + (uint32_t)(wn * 32 + ntp * 16) * QKSB + kbyte + bRow;
                uint32_t bh[4], bl[4];
                ldsm4(bh, kaddr);
                ldsm4(bl, kaddr + 9216u);
                #pragma unroll
                for (int mt = 0; mt < 2; mt++) {
                    mma16(cS[mt][2 * ntp],     ah[mt], bh[0], bh[1]);
                    mma16(cS[mt][2 * ntp],     al[mt], bh[0], bh[1]);
                    mma16(cS[mt][2 * ntp],     ah[mt], bl[0], bl[1]);
                    mma16(cS[mt][2 * ntp + 1], ah[mt], bh[2], bh[3]);
                    mma16(cS[mt][2 * ntp + 1], al[mt], bh[2], bh[3]);
                    mma16(cS[mt][2 * ntp + 1], ah[mt], bl[2], bl[3]);
                }
            }
        }

        // ---- warp-local partial row max ----
        float pm[2][2];
        #pragma unroll
        for (int mt = 0; mt < 2; mt++) {
            float m0 = -1e30f, m1 = -1e30f;
            #pragma unroll
            for (int nt = 0; nt < 4; nt++) {
                m0 = fmaxf(m0, fmaxf(cS[mt][nt][0], cS[mt][nt][1]));
                m1 = fmaxf(m1, fmaxf(cS[mt][nt][2], cS[mt][nt][3]));
            }
            m0 = fmaxf(m0, __shfl_xor_sync(0xffffffffu, m0, 1));
            m0 = fmaxf(m0, __shfl_xor_sync(0xffffffffu, m0, 2));
            m1 = fmaxf(m1, __shfl_xor_sync(0xffffffffu, m1, 1));
            m1 = fmaxf(m1, __shfl_xor_sync(0xffffffffu, m1, 2));
            pm[mt][0] = m0; pm[mt][1] = m1;
        }
        if (c4 == 0) {
            #pragma unroll
            for (int mt = 0; mt < 2; mt++) {
                int r = mrow + mt * 16 + r4;
                pmax[wn * 128 + r]     = pm[mt][0];
                pmax[wn * 128 + r + 8] = pm[mt][1];
            }
        }
        __syncthreads();   // sync_B: pmax visible; all warps done with K(jt)/S(jt)

        // ---- prefetch K(jt+1) into alt buffer ----
        if (jt < 63) {
            int j0n = (jt + 1) << 6;
            uint32_t kdst = sb + OFF_K + (uint32_t)((jt + 1) & 1) * KBUFB;
            #pragma unroll
            for (int i = 0; i < 4; i++) {
                int m = tid + i * 256;
                int r = (m & 511) >> 3, j = m & 7;
                if (m < 512)
                    cp16(kdst + (uint32_t)(r * QKSB + j * 16), &g_Kh[p][j0n + r][j * 8]);
                else
                    cp16(kdst + 9216u + (uint32_t)(r * QKSB + j * 16), &g_Kl[p][j0n + r][j * 8]);
            }
            CP_COMMIT();
        }

        // ---- combined max, alpha, O-rescale ----
        float m_new[2][2], alpha[2][2];
        #pragma unroll
        for (int mt = 0; mt < 2; mt++) {
            #pragma unroll
            for (int h = 0; h < 2; h++) {
                int r = mrow + mt * 16 + r4 + 8 * h;
                float mt_tile = fmaxf(pmax[r], pmax[128 + r]);
                m_new[mt][h] = fmaxf(m_run[mt][h], mt_tile);
                alpha[mt][h] = __expf(m_run[mt][h] - m_new[mt][h]);
                m_run[mt][h] = m_new[mt][h];
            }
        }
        bool anyr = (alpha[0][0] < 1.f) | (alpha[0][1] < 1.f)
                  | (alpha[1][0] < 1.f) | (alpha[1][1] < 1.f);
        if (__any_sync(0xffffffffu, anyr)) {
            #pragma unroll
            for (int mt = 0; mt < 2; mt++)
                #pragma unroll
                for (int nt = 0; nt < 16; nt++) {
                    O[mt][nt][0] *= alpha[mt][0];
                    O[mt][nt][1] *= alpha[mt][0];
                    O[mt][nt][2] *= alpha[mt][1];
                    O[mt][nt][3] *= alpha[mt][1];
                }
        }

        // ---- exp, pack fp16 P (kept in regs AND stored to smem) ----
        uint32_t pk[2][4][2];
        #pragma unroll
        for (int mt = 0; mt < 2; mt++) {
            int r = mrow + mt * 16 + r4;
            float s0 = 0.f, s1 = 0.f;
            #pragma unroll
            for (int nt = 0; nt < 4; nt++) {
                int col = wn * 32 + nt * 8 + 2 * c4;
                float e0 = __expf(cS[mt][nt][0] - m_new[mt][0]);
                float e1 = __expf(cS[mt][nt][1] - m_new[mt][0]);
                float e2 = __expf(cS[mt][nt][2] - m_new[mt][1]);
                float e3 = __expf(cS[mt][nt][3] - m_new[mt][1]);
                s0 += e0 + e1;
                s1 += e2 + e3;
                pk[mt][nt][0] = pack_f16(e0, e1);
                pk[mt][nt][1] = pack_f16(e2, e3);
                *(uint32_t*)(smem + OFF_P + r * QKSB + col * 2)       = pk[mt][nt][0];
                *(uint32_t*)(smem + OFF_P + (r + 8) * QKSB + col * 2) = pk[mt][nt][1];
            }
            lsum[mt][0] = lsum[mt][0] * alpha[mt][0] + s0;
            lsum[mt][1] = lsum[mt][1] * alpha[mt][1] + s1;
        }

        // ---- LOCAL-half PV from registers (V(jt) visible since last barrier) ----
        #pragma unroll
        for (int lc = 0; lc < 2; lc++) {
            uint32_t kbyte = (uint32_t)((wn * 2 + lc) * 32);
            uint32_t pa0[4] = { pk[0][2 * lc][0], pk[0][2 * lc][1],
                                pk[0][2 * lc + 1][0], pk[0][2 * lc + 1][1] };
            uint32_t pa1[4] = { pk[1][2 * lc][0], pk[1][2 * lc][1],
                                pk[1][2 * lc + 1][0], pk[1][2 * lc + 1][1] };
            #pragma unroll
            for (int ntp = 0; ntp < 8; ntp++) {
                uint32_t vaddr = vbase + (uint32_t)(wn * 128 + ntp * 16) * QKSB + kbyte + bRow;
                uint32_t vb[4];
                ldsm4(vb, vaddr);
                mma16f(O[0][2 * ntp],     pa0, vb[0], vb[1]);
                mma16f(O[1][2 * ntp],     pa1, vb[0], vb[1]);
                mma16f(O[0][2 * ntp + 1], pa0, vb[2], vb[3]);
                mma16f(O[1][2 * ntp + 1], pa1, vb[2], vb[3]);
            }
        }

        // own cp.asyncs (V(jt+1), K(jt+1)) must be complete before the barrier
        CP_WAIT(0);
        __syncthreads();   // sync_C: partner P visible; K(jt+1)/V(jt+1) published

        // ---- CROSS-half PV from smem P (partner's 32 cols) ----
        #pragma unroll
        for (int lc = 0; lc < 2; lc++) {
            uint32_t kbyte = (uint32_t)(((1 - wn) * 2 + lc) * 32);
            uint32_t pa[2][4];
            #pragma unroll
            for (int mt = 0; mt < 2; mt++) {
                uint32_t paddr = sb + OFF_P + (uint32_t)(mrow + mt * 16) * QKSB + kbyte + aRow;
                ldsm4(pa[mt], paddr);
            }
            #pragma unroll
            for (int ntp = 0; ntp < 8; ntp++) {
                uint32_t vaddr = vbase + (uint32_t)(wn * 128 + ntp * 16) * QKSB + kbyte + bRow;
                uint32_t vb[4];
                ldsm4(vb, vaddr);
                mma16f(O[0][2 * ntp],     pa[0], vb[0], vb[1]);
                mma16f(O[1][2 * ntp],     pa[1], vb[0], vb[1]);
                mma16f(O[0][2 * ntp + 1], pa[0], vb[2], vb[3]);
                mma16f(O[1][2 * ntp + 1], pa[1], vb[2], vb[3]);
            }
        }

        vc = vn;
    }

    // ---- row-sum reduction ----
    #pragma unroll
    for (int mt = 0; mt < 2; mt++)
        #pragma unroll
        for (int h = 0; h < 2; h++) {
            float v = lsum[mt][h];
            v += __shfl_xor_sync(0xffffffffu, v, 1);
            v += __shfl_xor_sync(0xffffffffu, v, 2);
            if (c4 == 0) atomicAdd(&lrow[mrow + mt * 16 + r4 + 8 * h], v);
        }
    __syncthreads();

    // ---- epilogue ----
    float gm = gamma[0];
    int s = p >> 1, b = p & 1;
    const float* xin = (s ? in2 : in1) + (size_t)b * CC * NPIX;
    float* o = out + (size_t)p * CC * NPIX;
    #pragma unroll
    for (int mt = 0; mt < 2; mt++) {
        int rlo = mrow + mt * 16 + r4, rhi = rlo + 8;
        float sclo = gm / lrow[rlo];
        float schi = gm / lrow[rhi];
        size_t nlo = (size_t)(i0 + rlo), nhi = (size_t)(i0 + rhi);
        #pragma unroll
        for (int nt = 0; nt < 16; nt++) {
            int ch = wn * 128 + nt * 8 + 2 * c4;
            o[(size_t)ch * NPIX + nlo]       = O[mt][nt][0] * sclo + xin[(size_t)ch * NPIX + nlo];
            o[(size_t)(ch + 1) * NPIX + nlo] = O[mt][nt][1] * sclo + xin[(size_t)(ch + 1) * NPIX + nlo];
            o[(size_t)ch * NPIX + nhi]       = O[mt][nt][2] * schi + xin[(size_t)ch * NPIX + nhi];
            o[(size_t)(ch + 1) * NPIX + nhi] = O[mt][nt][3] * schi + xin[(size_t)(ch + 1) * NPIX + nhi];
        }
    }
}

// ---------------------------------------------------------------------------
extern "C" void kernel_launch(void* const* d_in, const int* in_sizes, int n_in,
                              void* d_out, int out_size)
{
    const float* in1 = (const float*)d_in[0];
    const float* in2 = (const float*)d_in[1];
    const float* q1w = (const float*)d_in[2];  const float* q1b = (const float*)d_in[3];
    const float* k1w = (const float*)d_in[4];  const float* k1b = (const float*)d_in[5];
    const float* v1w = (const float*)d_in[6];  const float* v1b = (const float*)d_in[7];
    const float* q2w = (const float*)d_in[8];  const float* q2b = (const float*)d_in[9];
    const float* k2w = (const float*)d_in[10]; const float* k2b = (const float*)d_in[11];
    const float* v2w = (const float*)d_in[12]; const float* v2b = (const float*)d_in[13];
    const float* gamma = (const float*)d_in[22];
    float* out = (float*)d_out;

    prep_weights<<<dim3(384, 2), 256>>>(q1w, q1b, k1w, k1b, v1w, v1b,
                                        q2w, q2b, k2w, k2b, v2w, v2b);
    convert_x<<<dim3(64, 4, 4), 256>>>(in1, in2);

    cudaFuncSetAttribute(proj_mma, cudaFuncAttributeMaxDynamicSharedMemorySize, (int)PSMEM);
    proj_mma<<<dim3(32, 3, 4), 256, PSMEM>>>();

    cudaFuncSetAttribute(flash_attn, cudaFuncAttributeMaxDynamicSharedMemorySize, (int)SMEM_TOTAL);
    flash_attn<<<dim3(32, 4), 256, SMEM_TOTAL>>>(in1, in2, gamma, out);
}

// round 14
// speedup vs baseline: 1.3926x; 1.0809x over previous
#include <cuda_runtime.h>
#include <cuda_bf16.h>
#include <cuda_fp16.h>
#include <cstdint>

#define CC    256
#define CQ    64
#define NPIX  4096
#define NPAIR 4
#define LOG2E 1.4426950408889634f

// ---------------- helpers ----------------
__device__ __forceinline__ uint32_t smem_u32(const void* p) {
    uint32_t a;
    asm("{ .reg .u64 t; cvta.to.shared.u64 t, %1; cvt.u32.u64 %0, t; }" : "=r"(a) : "l"(p));
    return a;
}

__device__ __forceinline__ void cp16(uint32_t s, const void* g) {
    asm volatile("cp.async.cg.shared.global [%0], [%1], 16;" :: "r"(s), "l"(g) : "memory");
}
#define CP_COMMIT()  asm volatile("cp.async.commit_group;" ::: "memory")
#define CP_WAIT(N)   asm volatile("cp.async.wait_group %0;" :: "n"(N) : "memory")

// ldmatrix x4: four 8x8 b16 matrices -> 4 regs
__device__ __forceinline__ void ldsm4(uint32_t r[4], uint32_t addr) {
    asm volatile("ldmatrix.sync.aligned.m8n8.x4.shared.b16 {%0,%1,%2,%3}, [%4];"
        : "=r"(r[0]), "=r"(r[1]), "=r"(r[2]), "=r"(r[3]) : "r"(addr));
}

// m16n8k16 bf16 mma (S phase + proj)
__device__ __forceinline__ void mma16(float c[4], const uint32_t a[4], uint32_t b0, uint32_t b1) {
    asm volatile(
        "mma.sync.aligned.m16n8k16.row.col.f32.bf16.bf16.f32 "
        "{%0,%1,%2,%3}, {%4,%5,%6,%7}, {%8,%9}, {%0,%1,%2,%3};"
        : "+f"(c[0]), "+f"(c[1]), "+f"(c[2]), "+f"(c[3])
        : "r"(a[0]), "r"(a[1]), "r"(a[2]), "r"(a[3]), "r"(b0), "r"(b1));
}

// m16n8k16 fp16 mma (PV phase)
__device__ __forceinline__ void mma16f(float c[4], const uint32_t a[4], uint32_t b0, uint32_t b1) {
    asm volatile(
        "mma.sync.aligned.m16n8k16.row.col.f32.f16.f16.f32 "
        "{%0,%1,%2,%3}, {%4,%5,%6,%7}, {%8,%9}, {%0,%1,%2,%3};"
        : "+f"(c[0]), "+f"(c[1]), "+f"(c[2]), "+f"(c[3])
        : "r"(a[0]), "r"(a[1]), "r"(a[2]), "r"(a[3]), "r"(b0), "r"(b1));
}

__device__ __forceinline__ uint32_t pack_bf16(float a, float b) {
    __nv_bfloat16 h0 = __float2bfloat16(a), h1 = __float2bfloat16(b);
    uint16_t u0 = *(uint16_t*)&h0, u1 = *(uint16_t*)&h1;
    return ((uint32_t)u1 << 16) | u0;
}

__device__ __forceinline__ uint32_t pack_f16(float a, float b) {
    __half2 h = __floats2half2_rn(a, b);
    return *(uint32_t*)&h;
}

// ---------------- scratch ----------------
__device__ float g_Bias[2][384];
__device__ __nv_bfloat16 g_Wh[2][384][CC];
__device__ __nv_bfloat16 g_Wl[2][384][CC];
__device__ __nv_bfloat16 g_Xh[NPAIR][NPIX][CC];
__device__ __nv_bfloat16 g_Xl[NPAIR][NPIX][CC];
__device__ __nv_bfloat16 g_Qh[NPAIR][NPIX][CQ];   // scaled by log2(e)
__device__ __nv_bfloat16 g_Ql[NPAIR][NPIX][CQ];
__device__ __nv_bfloat16 g_Kh[NPAIR][NPIX][CQ];
__device__ __nv_bfloat16 g_Kl[NPAIR][NPIX][CQ];
__device__ __half g_V[NPAIR][CC][NPIX];           // channel-major fp16 V

// ---------------------------------------------------------------------------
__global__ void prep_weights(
    const float* __restrict__ q1w, const float* __restrict__ q1b,
    const float* __restrict__ k1w, const float* __restrict__ k1b,
    const float* __restrict__ v1w, const float* __restrict__ v1b,
    const float* __restrict__ q2w, const float* __restrict__ q2b,
    const float* __restrict__ k2w, const float* __restrict__ k2b,
    const float* __restrict__ v2w, const float* __restrict__ v2b)
{
    int o = blockIdx.x, s = blockIdx.y;
    const float* w; const float* bsrc; int row;
    if (o < 64)       { w = s ? q2w : q1w; bsrc = s ? q2b : q1b; row = o; }
    else if (o < 128) { w = s ? k2w : k1w; bsrc = s ? k2b : k1b; row = o - 64; }
    else              { w = s ? v2w : v1w; bsrc = s ? v2b : v1b; row = o - 128; }
    float v = w[row * CC + threadIdx.x];
    __nv_bfloat16 h = __float2bfloat16(v);
    g_Wh[s][o][threadIdx.x] = h;
    g_Wl[s][o][threadIdx.x] = __float2bfloat16(v - __bfloat162float(h));
    if (threadIdx.x == 0) g_Bias[s][o] = bsrc[row];
}

// ---------------------------------------------------------------------------
__global__ __launch_bounds__(256) void convert_x(
    const float* __restrict__ in1, const float* __restrict__ in2)
{
    __shared__ float t[64][65];
    int p = blockIdx.z, s = p >> 1, b = p & 1;
    const float* x = (s ? in2 : in1) + (size_t)b * CC * NPIX;
    int n0 = blockIdx.x * 64, c0 = blockIdx.y * 64;
    int tid = threadIdx.x;

    #pragma unroll
    for (int i = 0; i < 4; i++) {
        int m = tid + i * 256;
        int c = m >> 4, nn = (m & 15) << 2;
        float4 v = *(const float4*)&x[(size_t)(c0 + c) * NPIX + n0 + nn];
        t[c][nn] = v.x; t[c][nn + 1] = v.y; t[c][nn + 2] = v.z; t[c][nn + 3] = v.w;
    }
    __syncthreads();

    int n = tid >> 2, cb = (tid & 3) << 4;
    uint32_t hw[8], lw[8];
    #pragma unroll
    for (int j = 0; j < 8; j++) {
        float v0 = t[cb + 2 * j][n], v1 = t[cb + 2 * j + 1][n];
        __nv_bfloat16 h0 = __float2bfloat16(v0);
        __nv_bfloat16 h1 = __float2bfloat16(v1);
        float l0 = v0 - __bfloat162float(h0);
        float l1 = v1 - __bfloat162float(h1);
        uint16_t a0 = *(uint16_t*)&h0, a1 = *(uint16_t*)&h1;
        hw[j] = ((uint32_t)a1 << 16) | a0;
        lw[j] = pack_bf16(l0, l1);
    }
    uint4* dh = (uint4*)&g_Xh[p][n0 + n][c0 + cb];
    uint4* dl = (uint4*)&g_Xl[p][n0 + n][c0 + cb];
    dh[0] = make_uint4(hw[0], hw[1], hw[2], hw[3]);
    dh[1] = make_uint4(hw[4], hw[5], hw[6], hw[7]);
    dl[0] = make_uint4(lw[0], lw[1], lw[2], lw[3]);
    dl[1] = make_uint4(lw[4], lw[5], lw[6], lw[7]);
}

// ---------------------------------------------------------------------------
// Tensorized projection; Q epilogue pre-scales by log2(e) for base-2 softmax.
// ---------------------------------------------------------------------------
#define PJS 144u
#define PA_H 0u
#define PA_L 18432u
#define PB_H 36864u
#define PB_L 55296u
#define PSTAGE 73728u
#define POFF_BIAS 147456u
#define PSMEM 147968u

__global__ __launch_bounds__(256, 1) void proj_mma()
{
    extern __shared__ __align__(16) char psm[];
    uint32_t sb = smem_u32(psm);
    float* bias = (float*)(psm + POFF_BIAS);
    int tid = threadIdx.x;
    int p = blockIdx.z, s = p >> 1;
    int n0 = blockIdx.x * 128, o0 = blockIdx.y * 128;
    int warp = tid >> 5, lane = tid & 31;
    int wm = warp >> 1, wn = warp & 1;
    int r4 = lane >> 2, c4 = lane & 3;

    if (tid < 128) bias[tid] = g_Bias[s][o0 + tid];

    auto issue = [&](int kc) {
        uint32_t st = sb + (uint32_t)(kc & 1) * PSTAGE;
        int k0 = kc * 64;
        #pragma unroll
        for (int i = 0; i < 4; i++) {
            int m = tid + i * 256;
            int r = m >> 3, j = m & 7;
            uint32_t off = (uint32_t)r * PJS + (uint32_t)j * 16u;
            cp16(st + PA_H + off, &g_Xh[p][n0 + r][k0 + j * 8]);
            cp16(st + PA_L + off, &g_Xl[p][n0 + r][k0 + j * 8]);
            cp16(st + PB_H + off, &g_Wh[s][o0 + r][k0 + j * 8]);
            cp16(st + PB_L + off, &g_Wl[s][o0 + r][k0 + j * 8]);
        }
        CP_COMMIT();
    };
    issue(0);
    issue(1);

    float cS[2][8][4] = {};

    for (int kc = 0; kc < 4; kc++) {
        CP_WAIT(1);
        __syncthreads();
        const char* st = psm + (kc & 1) * PSTAGE;

        #pragma unroll
        for (int kt = 0; kt < 4; kt++) {
            int kb = kt * 32 + c4 * 4;
            uint32_t ah[2][4], al[2][4];
            #pragma unroll
            for (int mt = 0; mt < 2; mt++) {
                int r = wm * 32 + mt * 16 + r4;
                const char* a_h = st + PA_H + r * PJS + kb;
                const char* a_l = st + PA_L + r * PJS + kb;
                ah[mt][0] = *(const uint32_t*)a_h;
                ah[mt][1] = *(const uint32_t*)(a_h + 8 * PJS);
                ah[mt][2] = *(const uint32_t*)(a_h + 16);
                ah[mt][3] = *(const uint32_t*)(a_h + 8 * PJS + 16);
                al[mt][0] = *(const uint32_t*)a_l;
                al[mt][1] = *(const uint32_t*)(a_l + 8 * PJS);
                al[mt][2] = *(const uint32_t*)(a_l + 16);
                al[mt][3] = *(const uint32_t*)(a_l + 8 * PJS + 16);
            }
            #pragma unroll
            for (int nt = 0; nt < 8; nt++) {
                int o = wn * 64 + nt * 8 + r4;
                const char* b_h = st + PB_H + o * PJS + kb;
                const char* b_l = st + PB_L + o * PJS + kb;
                uint32_t bh0 = *(const uint32_t*)b_h;
                uint32_t bh1 = *(const uint32_t*)(b_h + 16);
                uint32_t bl0 = *(const uint32_t*)b_l;
                uint32_t bl1 = *(const uint32_t*)(b_l + 16);
                #pragma unroll
                for (int mt = 0; mt < 2; mt++) {
                    mma16(cS[mt][nt], ah[mt], bh0, bh1);
                    mma16(cS[mt][nt], al[mt], bh0, bh1);
                    mma16(cS[mt][nt], ah[mt], bl0, bl1);
                }
            }
        }
        __syncthreads();
        if (kc < 2) issue(kc + 2);
    }

    #pragma unroll
    for (int mt = 0; mt < 2; mt++) {
        int n_lo = n0 + wm * 32 + mt * 16 + r4;
        int n_hi = n_lo + 8;
        #pragma unroll
        for (int nt = 0; nt < 8; nt++) {
            int ol = wn * 64 + nt * 8 + 2 * c4;
            int og = o0 + ol;
            float b0 = bias[ol], b1 = bias[ol + 1];
            float y00 = cS[mt][nt][0] + b0, y01 = cS[mt][nt][1] + b1;
            float y10 = cS[mt][nt][2] + b0, y11 = cS[mt][nt][3] + b1;
            if (og < 64) {
                // base-2 softmax: scale Q by log2(e) before splitting
                y00 *= LOG2E; y01 *= LOG2E; y10 *= LOG2E; y11 *= LOG2E;
                __nv_bfloat16 h00 = __float2bfloat16(y00), h01 = __float2bfloat16(y01);
                __nv_bfloat16 h10 = __float2bfloat16(y10), h11 = __float2bfloat16(y11);
                uint16_t u00 = *(uint16_t*)&h00, u01 = *(uint16_t*)&h01;
                uint16_t u10 = *(uint16_t*)&h10, u11 = *(uint16_t*)&h11;
                *(uint32_t*)&g_Qh[p][n_lo][og] = ((uint32_t)u01 << 16) | u00;
                *(uint32_t*)&g_Qh[p][n_hi][og] = ((uint32_t)u11 << 16) | u10;
                *(uint32_t*)&g_Ql[p][n_lo][og] =
                    pack_bf16(y00 - __bfloat162float(h00), y01 - __bfloat162float(h01));
                *(uint32_t*)&g_Ql[p][n_hi][og] =
                    pack_bf16(y10 - __bfloat162float(h10), y11 - __bfloat162float(h11));
            } else if (og < 128) {
                int oo = og - 64;
                __nv_bfloat16 h00 = __float2bfloat16(y00), h01 = __float2bfloat16(y01);
                __nv_bfloat16 h10 = __float2bfloat16(y10), h11 = __float2bfloat16(y11);
                uint16_t u00 = *(uint16_t*)&h00, u01 = *(uint16_t*)&h01;
                uint16_t u10 = *(uint16_t*)&h10, u11 = *(uint16_t*)&h11;
                *(uint32_t*)&g_Kh[p][n_lo][oo] = ((uint32_t)u01 << 16) | u00;
                *(uint32_t*)&g_Kh[p][n_hi][oo] = ((uint32_t)u11 << 16) | u10;
                *(uint32_t*)&g_Kl[p][n_lo][oo] =
                    pack_bf16(y00 - __bfloat162float(h00), y01 - __bfloat162float(h01));
                *(uint32_t*)&g_Kl[p][n_hi][oo] =
                    pack_bf16(y10 - __bfloat162float(h10), y11 - __bfloat162float(h11));
            } else {
                int c = og - 128;
                g_V[p][c][n_lo]     = __float2half(y00);
                g_V[p][c + 1][n_lo] = __float2half(y01);
                g_V[p][c][n_hi]     = __float2half(y10);
                g_V[p][c + 1][n_hi] = __float2half(y11);
            }
        }
    }
}

// ---------------------------------------------------------------------------
// Flash attention: 128-row tiles, 8 warps (4M x 2N), 1 CTA/SM.
// ONE full-CTA barrier/tile + one PAIR barrier (bar.sync 1+wm, 64) for pmax.
// K double-buffered, V triple-buffered. Base-2 softmax (exp2f).
// PV split: local half from registers, cross half from smem P.
// ---------------------------------------------------------------------------
#define QKSB 144
#define KBUFB 18432u
#define OFF_K   0u
#define VBUFB  36864u
#define OFF_V0  36864u
#define OFF_QH 147456u
#define OFF_QL 165888u
#define OFF_P  184320u
#define OFF_L  202752u
#define OFF_PM 203264u
#define SMEM_TOTAL 204288u

__global__ __launch_bounds__(256, 1)
void flash_attn(const float* __restrict__ in1, const float* __restrict__ in2,
                const float* __restrict__ gamma, float* __restrict__ out)
{
    extern __shared__ __align__(16) char smem[];
    float* lrow = (float*)(smem + OFF_L);
    float* pmax = (float*)(smem + OFF_PM);
    uint32_t sb = smem_u32(smem);

    int tid  = threadIdx.x;
    int p    = blockIdx.y;
    int i0   = blockIdx.x * 128;
    int warp = tid >> 5, lane = tid & 31;
    int wm = warp >> 1, wn = warp & 1;       // 4M x 2N
    int r4 = lane >> 2, c4 = lane & 3;
    int lm = lane >> 3, lr = lane & 7;
    int mrow = wm * 32;

    uint32_t aRow = (uint32_t)((lm & 1) * 8 + lr) * QKSB + (uint32_t)((lm >> 1) * 16);
    uint32_t bRow = (uint32_t)((lm >> 1) * 8 + lr) * QKSB + (uint32_t)((lm & 1) * 16);

    if (tid < 128) lrow[tid] = 0.f;

    // ---- prologue: load Q, K(0), V(0); wait; publish ----
    {
        #pragma unroll
        for (int i = 0; i < 8; i++) {
            int m = tid + i * 256;
            int r = (m & 1023) >> 3, j = m & 7;
            if (m < 1024)
                cp16(sb + OFF_QH + (uint32_t)(r * QKSB + j * 16), &g_Qh[p][i0 + r][j * 8]);
            else
                cp16(sb + OFF_QL + (uint32_t)(r * QKSB + j * 16), &g_Ql[p][i0 + r][j * 8]);
        }
        #pragma unroll
        for (int i = 0; i < 4; i++) {
            int m = tid + i * 256;
            int r = (m & 511) >> 3, j = m & 7;
            if (m < 512)
                cp16(sb + OFF_K + (uint32_t)(r * QKSB + j * 16), &g_Kh[p][r][j * 8]);
            else
                cp16(sb + OFF_K + 9216u + (uint32_t)(r * QKSB + j * 16), &g_Kl[p][r][j * 8]);
        }
        #pragma unroll
        for (int i = 0; i < 8; i++) {
            int m = tid + i * 256;
            int ch = m >> 3, j = m & 7;
            cp16(sb + OFF_V0 + (uint32_t)(ch * QKSB + j * 16), &g_V[p][ch][j * 8]);
        }
        CP_COMMIT();
        CP_WAIT(0);
        __syncthreads();
    }

    float O[2][16][4];
    #pragma unroll
    for (int mt = 0; mt < 2; mt++)
        #pragma unroll
        for (int nt = 0; nt < 16; nt++)
            #pragma unroll
            for (int i = 0; i < 4; i++) O[mt][nt][i] = 0.f;

    float lsum[2][2] = {};
    float m_run[2][2] = {{-1e30f, -1e30f}, {-1e30f, -1e30f}};

    int vc = 0;

    for (int jt = 0; jt < 64; jt++) {
        uint32_t kbase = sb + OFF_K  + (uint32_t)(jt & 1) * KBUFB;
        uint32_t vbase = sb + OFF_V0 + (uint32_t)vc * VBUFB;
        int vn = vc + 1; if (vn == 3) vn = 0;

        // ---- prefetch V(jt+1) into third buffer ----
        if (jt < 63) {
            int j0n = (jt + 1) << 6;
            uint32_t vdst = sb + OFF_V0 + (uint32_t)vn * VBUFB;
            #pragma unroll
            for (int i = 0; i < 8; i++) {
                int m = tid + i * 256;
                int ch = m >> 3, j = m & 7;
                cp16(vdst + (uint32_t)(ch * QKSB + j * 16), &g_V[p][ch][j0n + j * 8]);
            }
            CP_COMMIT();
        }

        // ---- S = QK^T: 3-term split-bf16 (ldmatrix); logits in log2 units ----
        float cS[2][4][4];
        #pragma unroll
        for (int mt = 0; mt < 2; mt++)
            #pragma unroll
            for (int nt = 0; nt < 4; nt++)
                #pragma unroll
                for (int i = 0; i < 4; i++) cS[mt][nt][i] = 0.f;

        #pragma unroll
        for (int kt = 0; kt < 4; kt++) {
            uint32_t kbyte = (uint32_t)kt * 32u;
            uint32_t ah[2][4], al[2][4];
            #pragma unroll
            for (int mt = 0; mt < 2; mt++) {
                uint32_t qaddr = sb + OFF_QH + (uint32_t)(mrow + mt * 16) * QKSB + kbyte + aRow;
                ldsm4(ah[mt], qaddr);
                ldsm4(al[mt], qaddr + (OFF_QL - OFF_QH));
            }
            #pragma unroll
            for (int ntp = 0; ntp < 2; ntp++) {
                uint32_t kaddr = kbase + (uint32_t)(wn * 32 + ntp * 16) * QKSB + kbyte + bRow;
                uint32_t bh[4], bl[4];
                ldsm4(bh, kaddr);
                ldsm4(bl, kaddr + 9216u);
                #pragma unroll
                for (int mt = 0; mt < 2; mt++) {
                    mma16(cS[mt][2 * ntp],     ah[mt], bh[0], bh[1]);
                    mma16(cS[mt][2 * ntp],     al[mt], bh[0], bh[1]);
                    mma16(cS[mt][2 * ntp],     ah[mt], bl[0], bl[1]);
                    mma16(cS[mt][2 * ntp + 1], ah[mt], bh[2], bh[3]);
                    mma16(cS[mt][2 * ntp + 1], al[mt], bh[2], bh[3]);
                    mma16(cS[mt][2 * ntp + 1], ah[mt], bl[2], bl[3]);
                }
            }
        }

        // ---- warp-local partial row max ----
        float pm[2][2];
        #pragma unroll
        for (int mt = 0; mt < 2; mt++) {
            float m0 = -1e30f, m1 = -1e30f;
            #pragma unroll
            for (int nt = 0; nt < 4; nt++) {
                m0 = fmaxf(m0, fmaxf(cS[mt][nt][0], cS[mt][nt][1]));
                m1 = fmaxf(m1, fmaxf(cS[mt][nt][2], cS[mt][nt][3]));
            }
            m0 = fmaxf(m0, __shfl_xor_sync(0xffffffffu, m0, 1));
            m0 = fmaxf(m0, __shfl_xor_sync(0xffffffffu, m0, 2));
            m1 = fmaxf(m1, __shfl_xor_sync(0xffffffffu, m1, 1));
            m1 = fmaxf(m1, __shfl_xor_sync(0xffffffffu, m1, 2));
            pm[mt][0] = m0; pm[mt][1] = m1;
        }
        if (c4 == 0) {
            #pragma unroll
            for (int mt = 0; mt < 2; mt++) {
                int r = mrow + mt * 16 + r4;
                pmax[wn * 128 + r]     = pm[mt][0];
                pmax[wn * 128 + r + 8] = pm[mt][1];
            }
        }
        // PAIR barrier: only the 2 N-warps sharing these rows (64 threads)
        asm volatile("bar.sync %0, 64;" :: "r"(1 + wm) : "memory");

        // ---- prefetch K(jt+1) into alt buffer ----
        if (jt < 63) {
            int j0n = (jt + 1) << 6;
            uint32_t kdst = sb + OFF_K + (uint32_t)((jt + 1) & 1) * KBUFB;
            #pragma unroll
            for (int i = 0; i < 4; i++) {
                int m = tid + i * 256;
                int r = (m & 511) >> 3, j = m & 7;
                if (m < 512)
                    cp16(kdst + (uint32_t)(r * QKSB + j * 16), &g_Kh[p][j0n + r][j * 8]);
                else
                    cp16(kdst + 9216u + (uint32_t)(r * QKSB + j * 16), &g_Kl[p][j0n + r][j * 8]);
            }
            CP_COMMIT();
        }

        // ---- combined max, alpha (base-2), O-rescale ----
        float m_new[2][2], alpha[2][2];
        #pragma unroll
        for (int mt = 0; mt < 2; mt++) {
            #pragma unroll
            for (int h = 0; h < 2; h++) {
                int r = mrow + mt * 16 + r4 + 8 * h;
                float mt_tile = fmaxf(pmax[r], pmax[128 + r]);
                m_new[mt][h] = fmaxf(m_run[mt][h], mt_tile);
                alpha[mt][h] = exp2f(m_run[mt][h] - m_new[mt][h]);
                m_run[mt][h] = m_new[mt][h];
            }
        }
        bool anyr = (alpha[0][0] < 1.f) | (alpha[0][1] < 1.f)
                  | (alpha[1][0] < 1.f) | (alpha[1][1] < 1.f);
        if (__any_sync(0xffffffffu, anyr)) {
            #pragma unroll
            for (int mt = 0; mt < 2; mt++)
                #pragma unroll
                for (int nt = 0; nt < 16; nt++) {
                    O[mt][nt][0] *= alpha[mt][0];
                    O[mt][nt][1] *= alpha[mt][0];
                    O[mt][nt][2] *= alpha[mt][1];
                    O[mt][nt][3] *= alpha[mt][1];
                }
        }

        // ---- exp2, pack fp16 P (regs + smem) ----
        uint32_t pk[2][4][2];
        #pragma unroll
        for (int mt = 0; mt < 2; mt++) {
            int r = mrow + mt * 16 + r4;
            float s0 = 0.f, s1 = 0.f;
            #pragma unroll
            for (int nt = 0; nt < 4; nt++) {
                int col = wn * 32 + nt * 8 + 2 * c4;
                float e0 = exp2f(cS[mt][nt][0] - m_new[mt][0]);
                float e1 = exp2f(cS[mt][nt][1] - m_new[mt][0]);
                float e2 = exp2f(cS[mt][nt][2] - m_new[mt][1]);
                float e3 = exp2f(cS[mt][nt][3] - m_new[mt][1]);
                s0 += e0 + e1;
                s1 += e2 + e3;
                pk[mt][nt][0] = pack_f16(e0, e1);
                pk[mt][nt][1] = pack_f16(e2, e3);
                *(uint32_t*)(smem + OFF_P + r * QKSB + col * 2)       = pk[mt][nt][0];
                *(uint32_t*)(smem + OFF_P + (r + 8) * QKSB + col * 2) = pk[mt][nt][1];
            }
            lsum[mt][0] = lsum[mt][0] * alpha[mt][0] + s0;
            lsum[mt][1] = lsum[mt][1] * alpha[mt][1] + s1;
        }

        // ---- LOCAL-half PV from registers ----
        #pragma unroll
        for (int lc = 0; lc < 2; lc++) {
            uint32_t kbyte = (uint32_t)((wn * 2 + lc) * 32);
            uint32_t pa0[4] = { pk[0][2 * lc][0], pk[0][2 * lc][1],
                                pk[0][2 * lc + 1][0], pk[0][2 * lc + 1][1] };
            uint32_t pa1[4] = { pk[1][2 * lc][0], pk[1][2 * lc][1],
                                pk[1][2 * lc + 1][0], pk[1][2 * lc + 1][1] };
            #pragma unroll
            for (int ntp = 0; ntp < 8; ntp++) {
                uint32_t vaddr = vbase + (uint32_t)(wn * 128 + ntp * 16) * QKSB + kbyte + bRow;
                uint32_t vb[4];
                ldsm4(vb, vaddr);
                mma16f(O[0][2 * ntp],     pa0, vb[0], vb[1]);
                mma16f(O[1][2 * ntp],     pa1, vb[0], vb[1]);
                mma16f(O[0][2 * ntp + 1], pa0, vb[2], vb[3]);
                mma16f(O[1][2 * ntp + 1], pa1, vb[2], vb[3]);
            }
        }

        CP_WAIT(0);
        __syncthreads();   // sync_C: partner P visible; K(jt+1)/V(jt+1) published

        // ---- CROSS-half PV from smem P ----
        #pragma unroll
        for (int lc = 0; lc < 2; lc++) {
            uint32_t kbyte = (uint32_t)(((1 - wn) * 2 + lc) * 32);
            uint32_t pa[2][4];
            #pragma unroll
            for (int mt = 0; mt < 2; mt++) {
                uint32_t paddr = sb + OFF_P + (uint32_t)(mrow + mt * 16) * QKSB + kbyte + aRow;
                ldsm4(pa[mt], paddr);
            }
            #pragma unroll
            for (int ntp = 0; ntp < 8; ntp++) {
                uint32_t vaddr = vbase + (uint32_t)(wn * 128 + ntp * 16) * QKSB + kbyte + bRow;
                uint32_t vb[4];
                ldsm4(vb, vaddr);
                mma16f(O[0][2 * ntp],     pa[0], vb[0], vb[1]);
                mma16f(O[1][2 * ntp],     pa[1], vb[0], vb[1]);
                mma16f(O[0][2 * ntp + 1], pa[0], vb[2], vb[3]);
                mma16f(O[1][2 * ntp + 1], pa[1], vb[2], vb[3]);
            }
        }

        vc = vn;
    }

    // ---- row-sum reduction ----
    #pragma unroll
    for (int mt = 0; mt < 2; mt++)
        #pragma unroll
        for (int h = 0; h < 2; h++) {
            float v = lsum[mt][h];
            v += __shfl_xor_sync(0xffffffffu, v, 1);
            v += __shfl_xor_sync(0xffffffffu, v, 2);
            if (c4 == 0) atomicAdd(&lrow[mrow + mt * 16 + r4 + 8 * h], v);
        }
    __syncthreads();

    // ---- epilogue ----
    float gm = gamma[0];
    int s = p >> 1, b = p & 1;
    const float* xin = (s ? in2 : in1) + (size_t)b * CC * NPIX;
    float* o = out + (size_t)p * CC * NPIX;
    #pragma unroll
    for (int mt = 0; mt < 2; mt++) {
        int rlo = mrow + mt * 16 + r4, rhi = rlo + 8;
        float sclo = gm / lrow[rlo];
        float schi = gm / lrow[rhi];
        size_t nlo = (size_t)(i0 + rlo), nhi = (size_t)(i0 + rhi);
        #pragma unroll
        for (int nt = 0; nt < 16; nt++) {
            int ch = wn * 128 + nt * 8 + 2 * c4;
            o[(size_t)ch * NPIX + nlo]       = O[mt][nt][0] * sclo + xin[(size_t)ch * NPIX + nlo];
            o[(size_t)(ch + 1) * NPIX + nlo] = O[mt][nt][1] * sclo + xin[(size_t)(ch + 1) * NPIX + nlo];
            o[(size_t)ch * NPIX + nhi]       = O[mt][nt][2] * schi + xin[(size_t)ch * NPIX + nhi];
            o[(size_t)(ch + 1) * NPIX + nhi] = O[mt][nt][3] * schi + xin[(size_t)(ch + 1) * NPIX + nhi];
        }
    }
}

// ---------------------------------------------------------------------------
extern "C" void kernel_launch(void* const* d_in, const int* in_sizes, int n_in,
                              void* d_out, int out_size)
{
    const float* in1 = (const float*)d_in[0];
    const float* in2 = (const float*)d_in[1];
    const float* q1w = (const float*)d_in[2];  const float* q1b = (const float*)d_in[3];
    const float* k1w = (const float*)d_in[4];  const float* k1b = (const float*)d_in[5];
    const float* v1w = (const float*)d_in[6];  const float* v1b = (const float*)d_in[7];
    const float* q2w = (const float*)d_in[8];  const float* q2b = (const float*)d_in[9];
    const float* k2w = (const float*)d_in[10]; const float* k2b = (const float*)d_in[11];
    const float* v2w = (const float*)d_in[12]; const float* v2b = (const float*)d_in[13];
    const float* gamma = (const float*)d_in[22];
    float* out = (float*)d_out;

    prep_weights<<<dim3(384, 2), 256>>>(q1w, q1b, k1w, k1b, v1w, v1b,
                                        q2w, q2b, k2w, k2b, v2w, v2b);
    convert_x<<<dim3(64, 4, 4), 256>>>(in1, in2);

    cudaFuncSetAttribute(proj_mma, cudaFuncAttributeMaxDynamicSharedMemorySize, (int)PSMEM);
    proj_mma<<<dim3(32, 3, 4), 256, PSMEM>>>();

    cudaFuncSetAttribute(flash_attn, cudaFuncAttributeMaxDynamicSharedMemorySize, (int)SMEM_TOTAL);
    flash_attn<<<dim3(32, 4), 256, SMEM_TOTAL>>>(in1, in2, gamma, out);
}